// round 6
// baseline (speedup 1.0000x reference)
#include <cuda_runtime.h>
#include <cuda_bf16.h>
#include <cstdint>

// ============================================================================
// DoubleGRU on sm_100 (portable ISA): 13 chained 128x128x128 GEMMs per
// 128-row tile using mma.sync.m16n8k16 bf16 with fp32 hi/lo split.
// ============================================================================

#define THREADS 256
#define NTILES  1024
#define AST     136                  // tile stride in bf16 elements (padded)
#define TILE_BYTES (128 * AST * 2)   // 34816

// ---- smem layout (bytes) ----
#define SM_BIAS 0          // 768 floats
#define SM_XHI  4096
#define SM_XLO  (SM_XHI + TILE_BYTES)   // 38912
#define SM_HHI  (SM_XLO + TILE_BYTES)   // 73728
#define SM_HLO  (SM_HHI + TILE_BYTES)   // 108544
#define SM_W0   (SM_HLO + TILE_BYTES)   // 143360
#define SM_W1   (SM_W0 + TILE_BYTES)    // 178176
#define SM_TOTAL (SM_W1 + TILE_BYTES)   // 212992

// Pre-swizzled (transposed [n][k], padded to AST) weight images, hi/lo split.
// slots: 0-2 Wx1[i], 3-5 Wx2[i], 6-11 Wh[i], 12 mid
__device__ __align__(256) __nv_bfloat16 g_w_hi[13][128 * AST];
__device__ __align__(256) __nv_bfloat16 g_w_lo[13][128 * AST];

// ============================== PTX helpers ==============================
__device__ __forceinline__ uint32_t smem_to_u32(const void* p) {
    uint32_t a;
    asm("{ .reg .u64 t; cvta.to.shared.u64 t, %1; cvt.u32.u64 %0, t; }" : "=r"(a) : "l"(p));
    return a;
}

#define WAITG1 asm volatile("cp.async.wait_group 1;" ::: "memory")
#define WAITG0 asm volatile("cp.async.wait_group 0;" ::: "memory")
#define COMMITG asm volatile("cp.async.commit_group;" ::: "memory")

__device__ __forceinline__ void cp_async16(uint32_t dst, const void* src) {
    asm volatile("cp.async.cg.shared.global [%0], [%1], 16;" :: "r"(dst), "l"(src) : "memory");
}

__device__ __forceinline__ void ldm4(uint32_t* r, uint32_t addr) {
    asm volatile("ldmatrix.sync.aligned.m8n8.x4.shared.b16 {%0,%1,%2,%3}, [%4];"
        : "=r"(r[0]), "=r"(r[1]), "=r"(r[2]), "=r"(r[3]) : "r"(addr));
}

__device__ __forceinline__ void mma16816(float* c, const uint32_t* a, const uint32_t* b) {
    asm volatile("mma.sync.aligned.m16n8k16.row.col.f32.bf16.bf16.f32 "
        "{%0,%1,%2,%3}, {%4,%5,%6,%7}, {%8,%9}, {%0,%1,%2,%3};"
        : "+f"(c[0]), "+f"(c[1]), "+f"(c[2]), "+f"(c[3])
        : "r"(a[0]), "r"(a[1]), "r"(a[2]), "r"(a[3]), "r"(b[0]), "r"(b[1]));
}

// ============================== small math ==============================
__device__ __forceinline__ float sigm_f(float v) {
    v = fminf(fmaxf(v, -30.0f), 30.0f);
    return __fdividef(1.0f, 1.0f + __expf(-v));
}
__device__ __forceinline__ float tanh_f(float v) {
    v = fminf(fmaxf(v, -15.0f), 15.0f);
    float e = __expf(-2.0f * v);
    return __fdividef(1.0f - e, 1.0f + e);
}
__device__ __forceinline__ float2 bf2f(uint32_t u) {
    __nv_bfloat162 t = *reinterpret_cast<__nv_bfloat162*>(&u);
    return __bfloat1622float2(t);
}

// load/store fp32 pair via hi/lo bf16 tiles (col must be even)
__device__ __forceinline__ float2 lds_pairf(uint32_t hiT, uint32_t loT, int row, int col) {
    uint32_t off = (uint32_t)((row * AST + col) * 2);
    uint32_t h, l;
    asm volatile("ld.shared.u32 %0, [%1];" : "=r"(h) : "r"(hiT + off));
    asm volatile("ld.shared.u32 %0, [%1];" : "=r"(l) : "r"(loT + off));
    float2 a = bf2f(h), b = bf2f(l);
    return make_float2(a.x + b.x, a.y + b.y);
}
__device__ __forceinline__ void sts_pairf(uint32_t hiT, uint32_t loT, int row, int col, float2 v) {
    __nv_bfloat162 hb = __float22bfloat162_rn(v);
    float2 hf = __bfloat1622float2(hb);
    __nv_bfloat162 lb = __float22bfloat162_rn(make_float2(v.x - hf.x, v.y - hf.y));
    uint32_t off = (uint32_t)((row * AST + col) * 2);
    uint32_t hu = *reinterpret_cast<uint32_t*>(&hb);
    uint32_t lu = *reinterpret_cast<uint32_t*>(&lb);
    asm volatile("st.shared.u32 [%0], %1;" :: "r"(hiT + off), "r"(hu) : "memory");
    asm volatile("st.shared.u32 [%0], %1;" :: "r"(loT + off), "r"(lu) : "memory");
}

// ======================= weight prep (fp32 -> hi/lo, [n][k] padded) =======================
__global__ void prep_weights(const float* __restrict__ wx1, const float* __restrict__ wx2,
                             const float* __restrict__ wh, const float* __restrict__ mid) {
    int idx = blockIdx.x * blockDim.x + threadIdx.x;
    if (idx >= 13 * 128 * AST) return;
    int slot = idx / (128 * AST);
    int r = idx % (128 * AST);
    int n = r / AST;
    int k = r % AST;
    float v = 0.0f;
    if (k < 128) {
        const float* src;
        if (slot < 3)       src = wx1 + slot * 16384;
        else if (slot < 6)  src = wx2 + (slot - 3) * 16384;
        else if (slot < 12) src = wh + (slot - 6) * 16384;
        else                src = mid;
        v = src[k * 128 + n];   // W[k][n] -> B[n][k]
    }
    __nv_bfloat16 hb = __float2bfloat16(v);
    float hv = __bfloat162float(hb);
    __nv_bfloat16 lb = __float2bfloat16(v - hv);
    g_w_hi[slot][n * AST + k] = hb;
    g_w_lo[slot][n * AST + k] = lb;
}

// ======================= GEMM pass =======================
// pass1 (LO=true):  acc += Ah*B + Al*B   (B = hi weights in W0 buf)
// pass2 (LO=false): acc += Ah*B          (B = lo weights in W1 buf)
template <bool LO>
__device__ __forceinline__ void gemm_pass(uint32_t aH, uint32_t aL, uint32_t bB,
                                          float (*acc)[8][4]) {
#pragma unroll
    for (int k = 0; k < 8; k++) {
        uint32_t A0[4], A1[4], L0[4], L1[4];
        ldm4(A0, aH + k * 32);
        ldm4(A1, aH + 16 * AST * 2 + k * 32);
        if (LO) {
            ldm4(L0, aL + k * 32);
            ldm4(L1, aL + 16 * AST * 2 + k * 32);
        }
#pragma unroll
        for (int jj = 0; jj < 4; jj++) {
            uint32_t B[4];
            ldm4(B, bB + jj * (16 * AST * 2) + k * 32);
            mma16816(acc[0][2 * jj],     A0, B);
            mma16816(acc[0][2 * jj + 1], A0, B + 2);
            mma16816(acc[1][2 * jj],     A1, B);
            mma16816(acc[1][2 * jj + 1], A1, B + 2);
            if (LO) {
                mma16816(acc[0][2 * jj],     L0, B);
                mma16816(acc[0][2 * jj + 1], L0, B + 2);
                mma16816(acc[1][2 * jj],     L1, B);
                mma16816(acc[1][2 * jj + 1], L1, B + 2);
            }
        }
    }
}

__device__ __forceinline__ void issue_chunk(uint32_t sb, const __nv_bfloat16* src,
                                            int tid, int buf) {
    uint32_t dst = sb + (buf ? SM_W1 : SM_W0);
    const char* g = (const char*)src;
#pragma unroll
    for (int off = 0; off < TILE_BYTES; off += THREADS * 16) {
        int o = off + tid * 16;
        if (o < TILE_BYTES) cp_async16(dst + o, g + o);
    }
    COMMITG;
}

__device__ __forceinline__ void zero_acc(float (*acc)[8][4]) {
#pragma unroll
    for (int i = 0; i < 2; i++)
#pragma unroll
        for (int j = 0; j < 8; j++)
#pragma unroll
            for (int e = 0; e < 4; e++) acc[i][j][e] = 0.0f;
}

// ================================ main kernel ================================
__global__ void __launch_bounds__(THREADS, 1)
dgru_kernel(const float* __restrict__ x, const float* __restrict__ h_in,
            const float* __restrict__ bias_g, float* __restrict__ out) {
    extern __shared__ char smem[];
    uint32_t sb = smem_to_u32(smem);
    int tid  = threadIdx.x;
    int lane = tid & 31;
    int wm   = (tid >> 5) & 3;   // warp row (m block of 32)
    int wn   = tid >> 7;         // warp col half (n block of 64)
    int tile = blockIdx.x;

    // weight chunk source order (hi, lo per GEMM)
    const int wslot[13] = {2, 0, 6, 1, 7, 8, 12, 5, 3, 6, 4, 10, 11};
    const __nv_bfloat16* wsrc[26];
#pragma unroll
    for (int g = 0; g < 13; g++) {
        wsrc[2 * g]     = &g_w_hi[wslot[g]][0];
        wsrc[2 * g + 1] = &g_w_lo[wslot[g]][0];
    }

    // kick off first two weight chunks immediately
    issue_chunk(sb, wsrc[0], tid, 0);
    issue_chunk(sb, wsrc[1], tid, 1);

    // bias -> smem
    float* bias = (float*)(smem + SM_BIAS);
    for (int i = tid; i < 768; i += THREADS) bias[i] = bias_g[i];

    // prologue: x, old_h -> hi/lo bf16 tiles
    {
        int prow = tid >> 1, half = (tid & 1) * 64;
        const float4* px = (const float4*)(x    + ((size_t)tile * 128 + prow) * 128 + half);
        const float4* ph = (const float4*)(h_in + ((size_t)tile * 128 + prow) * 128 + half);
#pragma unroll
        for (int c4 = 0; c4 < 16; c4++) {
            float4 v = px[c4];
            sts_pairf(sb + SM_XHI, sb + SM_XLO, prow, half + c4 * 4,     make_float2(v.x, v.y));
            sts_pairf(sb + SM_XHI, sb + SM_XLO, prow, half + c4 * 4 + 2, make_float2(v.z, v.w));
            float4 u = ph[c4];
            sts_pairf(sb + SM_HHI, sb + SM_HLO, prow, half + c4 * 4,     make_float2(u.x, u.y));
            sts_pairf(sb + SM_HHI, sb + SM_HLO, prow, half + c4 * 4 + 2, make_float2(u.z, u.w));
        }
    }

    // per-thread ldmatrix base offsets (bytes within a tile)
    int aro = (lane & 7) + ((lane >> 3) & 1) * 8;
    int ako = ((lane >> 4) & 1) * 8;
    int bro = (lane & 7) + ((lane >> 4) & 1) * 8;
    int bko = ((lane >> 3) & 1) * 8;
    uint32_t aoff = (uint32_t)(((wm * 32 + aro) * AST + ako) * 2);
    uint32_t boff = (uint32_t)(((wn * 64 + bro) * AST + bko) * 2);

    float accA[2][8][4], accB[2][8][4];

    // epilogue element coordinates
    int erow = wm * 32 + (lane >> 2);        // + i*16 (+8 for regs 2,3)
    int ecol = wn * 64 + (lane & 3) * 2;     // + j*8
    float* otile = out + (size_t)tile * 128 * 128;

    // one GEMM (both passes) with chunk pipelining
#define GEMM_STEP(ACC, AHI, ALO, G) do {                                        \
        WAITG1; __syncthreads();                                                \
        gemm_pass<true>(sb + (AHI) + aoff, sb + (ALO) + aoff, sb + SM_W0 + boff, ACC); \
        __syncthreads();                                                        \
        if ((G) < 12) issue_chunk(sb, wsrc[2 * (G) + 2], tid, 0);               \
        if ((G) < 12) { WAITG1; } else { WAITG0; }                              \
        __syncthreads();                                                        \
        gemm_pass<false>(sb + (AHI) + aoff, 0u, sb + SM_W1 + boff, ACC);        \
        __syncthreads();                                                        \
        if ((G) < 12) issue_chunk(sb, wsrc[2 * (G) + 3], tid, 1);               \
    } while (0)

    // ---------------- stage 1 ----------------
    zero_acc(accA);
    GEMM_STEP(accA, SM_XHI, SM_XLO, 0);          // A  = x @ Wx1[2]
    zero_acc(accB);
    GEMM_STEP(accB, SM_XHI, SM_XLO, 1);          // B  = x @ Wx1[0]
    GEMM_STEP(accB, SM_HHI, SM_HLO, 2);          // B += h @ Wh[0]
    // epi: z = sigmoid(B + b0) -> OUT scratch
#pragma unroll
    for (int i = 0; i < 2; i++)
#pragma unroll
        for (int j = 0; j < 8; j++) {
            int r0 = erow + i * 16, c = ecol + j * 8;
            float2 z0 = make_float2(sigm_f(accB[i][j][0] + bias[c]),
                                    sigm_f(accB[i][j][1] + bias[c + 1]));
            float2 z1 = make_float2(sigm_f(accB[i][j][2] + bias[c]),
                                    sigm_f(accB[i][j][3] + bias[c + 1]));
            *(float2*)(otile + (size_t)r0 * 128 + c)       = z0;
            *(float2*)(otile + (size_t)(r0 + 8) * 128 + c) = z1;
        }

    zero_acc(accB);
    GEMM_STEP(accB, SM_XHI, SM_XLO, 3);          // B  = x @ Wx1[1]
    GEMM_STEP(accB, SM_HHI, SM_HLO, 4);          // B += h @ Wh[1]
    // epi: r = sigmoid(B + b1); rh = r * old_h -> X tiles
#pragma unroll
    for (int i = 0; i < 2; i++)
#pragma unroll
        for (int j = 0; j < 8; j++) {
            int r0 = erow + i * 16, c = ecol + j * 8;
            float2 oh0 = lds_pairf(sb + SM_HHI, sb + SM_HLO, r0, c);
            float2 oh1 = lds_pairf(sb + SM_HHI, sb + SM_HLO, r0 + 8, c);
            float2 v0 = make_float2(sigm_f(accB[i][j][0] + bias[128 + c]) * oh0.x,
                                    sigm_f(accB[i][j][1] + bias[128 + c + 1]) * oh0.y);
            float2 v1 = make_float2(sigm_f(accB[i][j][2] + bias[128 + c]) * oh1.x,
                                    sigm_f(accB[i][j][3] + bias[128 + c + 1]) * oh1.y);
            sts_pairf(sb + SM_XHI, sb + SM_XLO, r0, c, v0);
            sts_pairf(sb + SM_XHI, sb + SM_XLO, r0 + 8, c, v1);
        }
    // (sync happens at the top of next GEMM_STEP)

    GEMM_STEP(accA, SM_XHI, SM_XLO, 5);          // A += rh @ Wh[2]
    // epi: ht = tanh(A + b2); z from OUT; mid_h = z*oh + (1-z)*ht -> H tiles
#pragma unroll
    for (int i = 0; i < 2; i++)
#pragma unroll
        for (int j = 0; j < 8; j++) {
            int r0 = erow + i * 16, c = ecol + j * 8;
#pragma unroll
            for (int half = 0; half < 2; half++) {
                int r = r0 + half * 8;
                float2 oh = lds_pairf(sb + SM_HHI, sb + SM_HLO, r, c);
                float2 z  = *(const float2*)(otile + (size_t)r * 128 + c);
                float ht0 = tanh_f(accA[i][j][2 * half]     + bias[256 + c]);
                float ht1 = tanh_f(accA[i][j][2 * half + 1] + bias[256 + c + 1]);
                float2 mh = make_float2(z.x * oh.x + (1.0f - z.x) * ht0,
                                        z.y * oh.y + (1.0f - z.y) * ht1);
                sts_pairf(sb + SM_HHI, sb + SM_HLO, r, c, mh);
            }
        }

    zero_acc(accA);
    GEMM_STEP(accA, SM_HHI, SM_HLO, 6);          // A = mid_h @ mid
    // epi: mid_x = relu(A) -> X tiles
#pragma unroll
    for (int i = 0; i < 2; i++)
#pragma unroll
        for (int j = 0; j < 8; j++) {
            int r0 = erow + i * 16, c = ecol + j * 8;
            sts_pairf(sb + SM_XHI, sb + SM_XLO, r0, c,
                      make_float2(fmaxf(accA[i][j][0], 0.0f), fmaxf(accA[i][j][1], 0.0f)));
            sts_pairf(sb + SM_XHI, sb + SM_XLO, r0 + 8, c,
                      make_float2(fmaxf(accA[i][j][2], 0.0f), fmaxf(accA[i][j][3], 0.0f)));
        }

    // ---------------- stage 2 ----------------
    zero_acc(accA);
    GEMM_STEP(accA, SM_XHI, SM_XLO, 7);          // A  = mid_x @ Wx2[2]
    zero_acc(accB);
    GEMM_STEP(accB, SM_XHI, SM_XLO, 8);          // B  = mid_x @ Wx2[0]
    GEMM_STEP(accB, SM_HHI, SM_HLO, 9);          // B += mid_h @ Wh[0]
    // epi: z2 = sigmoid(B + b0) -> OUT scratch
#pragma unroll
    for (int i = 0; i < 2; i++)
#pragma unroll
        for (int j = 0; j < 8; j++) {
            int r0 = erow + i * 16, c = ecol + j * 8;
            float2 z0 = make_float2(sigm_f(accB[i][j][0] + bias[c]),
                                    sigm_f(accB[i][j][1] + bias[c + 1]));
            float2 z1 = make_float2(sigm_f(accB[i][j][2] + bias[c]),
                                    sigm_f(accB[i][j][3] + bias[c + 1]));
            *(float2*)(otile + (size_t)r0 * 128 + c)       = z0;
            *(float2*)(otile + (size_t)(r0 + 8) * 128 + c) = z1;
        }

    zero_acc(accB);
    GEMM_STEP(accB, SM_XHI, SM_XLO, 10);         // B  = mid_x @ Wx2[1]
    GEMM_STEP(accB, SM_HHI, SM_HLO, 11);         // B += mid_h @ Wh[4]
    // epi: r2 = sigmoid(B + b4); r2h = r2 * mid_h -> X tiles
#pragma unroll
    for (int i = 0; i < 2; i++)
#pragma unroll
        for (int j = 0; j < 8; j++) {
            int r0 = erow + i * 16, c = ecol + j * 8;
            float2 mh0 = lds_pairf(sb + SM_HHI, sb + SM_HLO, r0, c);
            float2 mh1 = lds_pairf(sb + SM_HHI, sb + SM_HLO, r0 + 8, c);
            float2 v0 = make_float2(sigm_f(accB[i][j][0] + bias[512 + c]) * mh0.x,
                                    sigm_f(accB[i][j][1] + bias[512 + c + 1]) * mh0.y);
            float2 v1 = make_float2(sigm_f(accB[i][j][2] + bias[512 + c]) * mh1.x,
                                    sigm_f(accB[i][j][3] + bias[512 + c + 1]) * mh1.y);
            sts_pairf(sb + SM_XHI, sb + SM_XLO, r0, c, v0);
            sts_pairf(sb + SM_XHI, sb + SM_XLO, r0 + 8, c, v1);
        }

    GEMM_STEP(accA, SM_XHI, SM_XLO, 12);         // A += r2h @ Wh[5]
    // final epi: h2t = tanh(A + b5); z2 from OUT; h = z2*mid_h + (1-z2)*h2t -> OUT
#pragma unroll
    for (int i = 0; i < 2; i++)
#pragma unroll
        for (int j = 0; j < 8; j++) {
            int r0 = erow + i * 16, c = ecol + j * 8;
#pragma unroll
            for (int half = 0; half < 2; half++) {
                int r = r0 + half * 8;
                float2 mh = lds_pairf(sb + SM_HHI, sb + SM_HLO, r, c);
                float2 z  = *(const float2*)(otile + (size_t)r * 128 + c);
                float t0 = tanh_f(accA[i][j][2 * half]     + bias[640 + c]);
                float t1 = tanh_f(accA[i][j][2 * half + 1] + bias[640 + c + 1]);
                float2 h = make_float2(z.x * mh.x + (1.0f - z.x) * t0,
                                       z.y * mh.y + (1.0f - z.y) * t1);
                *(float2*)(otile + (size_t)r * 128 + c) = h;
            }
        }
#undef GEMM_STEP
}

// ================================ launch ================================
extern "C" void kernel_launch(void* const* d_in, const int* in_sizes, int n_in,
                              void* d_out, int out_size) {
    const float* x   = (const float*)d_in[0];
    const float* oh  = (const float*)d_in[1];
    const float* wx1 = (const float*)d_in[2];
    const float* wx2 = (const float*)d_in[3];
    const float* wh  = (const float*)d_in[4];
    const float* b   = (const float*)d_in[5];
    const float* mid = (const float*)d_in[6];
    float* out = (float*)d_out;

    cudaFuncSetAttribute(dgru_kernel, cudaFuncAttributeMaxDynamicSharedMemorySize, SM_TOTAL);
    prep_weights<<<(13 * 128 * AST + 255) / 256, 256>>>(wx1, wx2, wh, mid);
    dgru_kernel<<<NTILES, THREADS, SM_TOTAL>>>(x, oh, b, out);
}

// round 9
// speedup vs baseline: 1.1372x; 1.1372x over previous
#include <cuda_runtime.h>
#include <cuda_bf16.h>
#include <cstdint>

// ============================================================================
// DoubleGRU on sm_100 (portable ISA): 13 chained 128x128x128 GEMMs per
// 128-row tile using mma.sync.m16n8k16 bf16 with fp32 hi/lo split.
// R8: 512 threads (16 warps, 4/SMSP), m32n32 warp tiles, compile-time weight
// table (device constexpr), 128-reg budget -> no spills, better latency hiding.
// ============================================================================

#define THREADS 512
#define NTILES  1024
#define AST     136                  // tile stride in bf16 elements (padded)
#define TILE_BYTES (128 * AST * 2)   // 34816

// ---- smem layout (bytes) ----
#define SM_BIAS 0          // 768 floats
#define SM_XHI  4096
#define SM_XLO  (SM_XHI + TILE_BYTES)   // 38912
#define SM_HHI  (SM_XLO + TILE_BYTES)   // 73728
#define SM_HLO  (SM_HHI + TILE_BYTES)   // 108544
#define SM_W0   (SM_HLO + TILE_BYTES)   // 143360
#define SM_W1   (SM_W0 + TILE_BYTES)    // 178176
#define SM_TOTAL (SM_W1 + TILE_BYTES)   // 212992

// Weight GEMM order (see schedule below); chunk g uses slot WSLOT[g].
// slots: 0-2 Wx1[i], 3-5 Wx2[i], 6-11 Wh[i], 12 mid
__device__ constexpr int WSLOT[13] = {2, 0, 6, 1, 7, 8, 12, 5, 3, 6, 4, 10, 11};

// Pre-transposed ([n][k], padded to AST) weight images, hi/lo split.
__device__ __align__(256) __nv_bfloat16 g_w_hi[13][128 * AST];
__device__ __align__(256) __nv_bfloat16 g_w_lo[13][128 * AST];

// ============================== PTX helpers ==============================
__device__ __forceinline__ uint32_t smem_to_u32(const void* p) {
    uint32_t a;
    asm("{ .reg .u64 t; cvta.to.shared.u64 t, %1; cvt.u32.u64 %0, t; }" : "=r"(a) : "l"(p));
    return a;
}

#define WAITG1 asm volatile("cp.async.wait_group 1;" ::: "memory")
#define WAITG0 asm volatile("cp.async.wait_group 0;" ::: "memory")
#define COMMITG asm volatile("cp.async.commit_group;" ::: "memory")

__device__ __forceinline__ void cp_async16(uint32_t dst, const void* src) {
    asm volatile("cp.async.cg.shared.global [%0], [%1], 16;" :: "r"(dst), "l"(src) : "memory");
}

__device__ __forceinline__ void ldm4(uint32_t* r, uint32_t addr) {
    asm volatile("ldmatrix.sync.aligned.m8n8.x4.shared.b16 {%0,%1,%2,%3}, [%4];"
        : "=r"(r[0]), "=r"(r[1]), "=r"(r[2]), "=r"(r[3]) : "r"(addr));
}

__device__ __forceinline__ void mma16816(float* c, const uint32_t* a, const uint32_t* b) {
    asm volatile("mma.sync.aligned.m16n8k16.row.col.f32.bf16.bf16.f32 "
        "{%0,%1,%2,%3}, {%4,%5,%6,%7}, {%8,%9}, {%0,%1,%2,%3};"
        : "+f"(c[0]), "+f"(c[1]), "+f"(c[2]), "+f"(c[3])
        : "r"(a[0]), "r"(a[1]), "r"(a[2]), "r"(a[3]), "r"(b[0]), "r"(b[1]));
}

// ============================== small math ==============================
__device__ __forceinline__ float sigm_f(float v) {
    v = fminf(fmaxf(v, -30.0f), 30.0f);
    return __fdividef(1.0f, 1.0f + __expf(-v));
}
__device__ __forceinline__ float tanh_f(float v) {
    v = fminf(fmaxf(v, -15.0f), 15.0f);
    float e = __expf(-2.0f * v);
    return __fdividef(1.0f - e, 1.0f + e);
}
__device__ __forceinline__ float2 bf2f(uint32_t u) {
    __nv_bfloat162 t = *reinterpret_cast<__nv_bfloat162*>(&u);
    return __bfloat1622float2(t);
}

// load/store fp32 pair via hi/lo bf16 tiles (col must be even)
__device__ __forceinline__ float2 lds_pairf(uint32_t hiT, uint32_t loT, int row, int col) {
    uint32_t off = (uint32_t)((row * AST + col) * 2);
    uint32_t h, l;
    asm volatile("ld.shared.u32 %0, [%1];" : "=r"(h) : "r"(hiT + off));
    asm volatile("ld.shared.u32 %0, [%1];" : "=r"(l) : "r"(loT + off));
    float2 a = bf2f(h), b = bf2f(l);
    return make_float2(a.x + b.x, a.y + b.y);
}
__device__ __forceinline__ void sts_pairf(uint32_t hiT, uint32_t loT, int row, int col, float2 v) {
    __nv_bfloat162 hb = __float22bfloat162_rn(v);
    float2 hf = __bfloat1622float2(hb);
    __nv_bfloat162 lb = __float22bfloat162_rn(make_float2(v.x - hf.x, v.y - hf.y));
    uint32_t off = (uint32_t)((row * AST + col) * 2);
    uint32_t hu = *reinterpret_cast<uint32_t*>(&hb);
    uint32_t lu = *reinterpret_cast<uint32_t*>(&lb);
    asm volatile("st.shared.u32 [%0], %1;" :: "r"(hiT + off), "r"(hu) : "memory");
    asm volatile("st.shared.u32 [%0], %1;" :: "r"(loT + off), "r"(lu) : "memory");
}

// ======================= weight prep (fp32 -> hi/lo, [n][k] padded) =======================
__global__ void prep_weights(const float* __restrict__ wx1, const float* __restrict__ wx2,
                             const float* __restrict__ wh, const float* __restrict__ mid) {
    int idx = blockIdx.x * blockDim.x + threadIdx.x;
    if (idx >= 13 * 128 * AST) return;
    int slot = idx / (128 * AST);
    int r = idx % (128 * AST);
    int n = r / AST;
    int k = r % AST;
    float v = 0.0f;
    if (k < 128) {
        const float* src;
        if (slot < 3)       src = wx1 + slot * 16384;
        else if (slot < 6)  src = wx2 + (slot - 3) * 16384;
        else if (slot < 12) src = wh + (slot - 6) * 16384;
        else                src = mid;
        v = src[k * 128 + n];   // W[k][n] -> B[n][k]
    }
    __nv_bfloat16 hb = __float2bfloat16(v);
    float hv = __bfloat162float(hb);
    __nv_bfloat16 lb = __float2bfloat16(v - hv);
    g_w_hi[slot][n * AST + k] = hb;
    g_w_lo[slot][n * AST + k] = lb;
}

// ======================= GEMM pass (m32n32 warp tile) =======================
// pass1 (LO=true):  acc += Ah*B + Al*B   (B = hi weights in W0 buf)
// pass2 (LO=false): acc += Ah*B          (B = lo weights in W1 buf)
template <bool LO>
__device__ __forceinline__ void gemm_pass(uint32_t aH, uint32_t aL, uint32_t bB,
                                          float (*acc)[4][4]) {
#pragma unroll
    for (int k = 0; k < 8; k++) {
        uint32_t A0[4], A1[4], B0[4], B1[4];
        ldm4(A0, aH + k * 32);
        ldm4(A1, aH + 16 * AST * 2 + k * 32);
        ldm4(B0, bB + k * 32);
        ldm4(B1, bB + 16 * AST * 2 + k * 32);
        mma16816(acc[0][0], A0, B0);
        mma16816(acc[0][1], A0, B0 + 2);
        mma16816(acc[0][2], A0, B1);
        mma16816(acc[0][3], A0, B1 + 2);
        mma16816(acc[1][0], A1, B0);
        mma16816(acc[1][1], A1, B0 + 2);
        mma16816(acc[1][2], A1, B1);
        mma16816(acc[1][3], A1, B1 + 2);
        if (LO) {
            uint32_t L0[4], L1[4];
            ldm4(L0, aL + k * 32);
            ldm4(L1, aL + 16 * AST * 2 + k * 32);
            mma16816(acc[0][0], L0, B0);
            mma16816(acc[0][1], L0, B0 + 2);
            mma16816(acc[0][2], L0, B1);
            mma16816(acc[0][3], L0, B1 + 2);
            mma16816(acc[1][0], L1, B0);
            mma16816(acc[1][1], L1, B0 + 2);
            mma16816(acc[1][2], L1, B1);
            mma16816(acc[1][3], L1, B1 + 2);
        }
    }
}

__device__ __forceinline__ void issue_chunk(uint32_t sb, const __nv_bfloat16* src,
                                            int tid, int buf) {
    uint32_t dst = sb + (buf ? SM_W1 : SM_W0);
    const char* g = (const char*)src;
#pragma unroll
    for (int off = 0; off < TILE_BYTES; off += THREADS * 16) {
        int o = off + tid * 16;
        if (o < TILE_BYTES) cp_async16(dst + o, g + o);
    }
    COMMITG;
}

__device__ __forceinline__ void zero_acc(float (*acc)[4][4]) {
#pragma unroll
    for (int i = 0; i < 2; i++)
#pragma unroll
        for (int j = 0; j < 4; j++)
#pragma unroll
            for (int e = 0; e < 4; e++) acc[i][j][e] = 0.0f;
}

// ================================ main kernel ================================
__global__ void __launch_bounds__(THREADS, 1)
dgru_kernel(const float* __restrict__ x, const float* __restrict__ h_in,
            const float* __restrict__ bias_g, float* __restrict__ out) {
    extern __shared__ char smem[];
    uint32_t sb = smem_to_u32(smem);
    int tid  = threadIdx.x;
    int lane = tid & 31;
    int wid  = tid >> 5;
    int wm   = wid & 3;    // warp m block (32 rows)
    int wn   = wid >> 2;   // warp n block (32 cols)
    int tile = blockIdx.x;

    // kick off first two weight chunks immediately (hi->W0, lo->W1 of GEMM 0)
    issue_chunk(sb, &g_w_hi[WSLOT[0]][0], tid, 0);
    issue_chunk(sb, &g_w_lo[WSLOT[0]][0], tid, 1);

    // bias -> smem
    float* bias = (float*)(smem + SM_BIAS);
    for (int i = tid; i < 768; i += THREADS) bias[i] = bias_g[i];

    // prologue: x, old_h -> hi/lo bf16 tiles (each thread: 1 row x 32 cols)
    {
        int prow = tid >> 2, half = (tid & 3) * 32;
        const float4* px = (const float4*)(x    + ((size_t)tile * 128 + prow) * 128 + half);
        const float4* ph = (const float4*)(h_in + ((size_t)tile * 128 + prow) * 128 + half);
#pragma unroll
        for (int c4 = 0; c4 < 8; c4++) {
            float4 v = px[c4];
            sts_pairf(sb + SM_XHI, sb + SM_XLO, prow, half + c4 * 4,     make_float2(v.x, v.y));
            sts_pairf(sb + SM_XHI, sb + SM_XLO, prow, half + c4 * 4 + 2, make_float2(v.z, v.w));
            float4 u = ph[c4];
            sts_pairf(sb + SM_HHI, sb + SM_HLO, prow, half + c4 * 4,     make_float2(u.x, u.y));
            sts_pairf(sb + SM_HHI, sb + SM_HLO, prow, half + c4 * 4 + 2, make_float2(u.z, u.w));
        }
    }

    // per-thread ldmatrix base offsets (bytes within a tile)
    int aro = (lane & 7) + ((lane >> 3) & 1) * 8;
    int ako = ((lane >> 4) & 1) * 8;
    int bro = (lane & 7) + ((lane >> 4) & 1) * 8;
    int bko = ((lane >> 3) & 1) * 8;
    uint32_t aoff = (uint32_t)(((wm * 32 + aro) * AST + ako) * 2);
    uint32_t boff = (uint32_t)(((wn * 32 + bro) * AST + bko) * 2);

    float accA[2][4][4], accB[2][4][4];

    // epilogue element coordinates
    int erow = wm * 32 + (lane >> 2);        // + i*16 (+8 for regs 2,3)
    int ecol = wn * 32 + (lane & 3) * 2;     // + j*8
    float* otile = out + (size_t)tile * 128 * 128;

    // one GEMM (both passes) with chunk pipelining.
    // buf0 always holds hi-weight chunks, buf1 always lo-weight chunks.
#define GEMM_STEP(ACC, AHI, ALO, G) do {                                        \
        WAITG1; __syncthreads();                                                \
        gemm_pass<true>(sb + (AHI) + aoff, sb + (ALO) + aoff, sb + SM_W0 + boff, ACC); \
        __syncthreads();                                                        \
        if ((G) < 12) issue_chunk(sb, &g_w_hi[WSLOT[(G) + 1]][0], tid, 0);      \
        if ((G) < 12) { WAITG1; } else { WAITG0; }                              \
        __syncthreads();                                                        \
        gemm_pass<false>(sb + (AHI) + aoff, 0u, sb + SM_W1 + boff, ACC);        \
        __syncthreads();                                                        \
        if ((G) < 12) issue_chunk(sb, &g_w_lo[WSLOT[(G) + 1]][0], tid, 1);      \
    } while (0)

    // ---------------- stage 1 ----------------
    zero_acc(accA);
    GEMM_STEP(accA, SM_XHI, SM_XLO, 0);          // A  = x @ Wx1[2]
    zero_acc(accB);
    GEMM_STEP(accB, SM_XHI, SM_XLO, 1);          // B  = x @ Wx1[0]
    GEMM_STEP(accB, SM_HHI, SM_HLO, 2);          // B += h @ Wh[0]
    // epi: z = sigmoid(B + b0) -> OUT scratch
#pragma unroll
    for (int i = 0; i < 2; i++)
#pragma unroll
        for (int j = 0; j < 4; j++) {
            int r0 = erow + i * 16, c = ecol + j * 8;
            float2 z0 = make_float2(sigm_f(accB[i][j][0] + bias[c]),
                                    sigm_f(accB[i][j][1] + bias[c + 1]));
            float2 z1 = make_float2(sigm_f(accB[i][j][2] + bias[c]),
                                    sigm_f(accB[i][j][3] + bias[c + 1]));
            *(float2*)(otile + (size_t)r0 * 128 + c)       = z0;
            *(float2*)(otile + (size_t)(r0 + 8) * 128 + c) = z1;
        }

    zero_acc(accB);
    GEMM_STEP(accB, SM_XHI, SM_XLO, 3);          // B  = x @ Wx1[1]
    GEMM_STEP(accB, SM_HHI, SM_HLO, 4);          // B += h @ Wh[1]
    // epi: r = sigmoid(B + b1); rh = r * old_h -> X tiles
#pragma unroll
    for (int i = 0; i < 2; i++)
#pragma unroll
        for (int j = 0; j < 4; j++) {
            int r0 = erow + i * 16, c = ecol + j * 8;
            float2 oh0 = lds_pairf(sb + SM_HHI, sb + SM_HLO, r0, c);
            float2 oh1 = lds_pairf(sb + SM_HHI, sb + SM_HLO, r0 + 8, c);
            float2 v0 = make_float2(sigm_f(accB[i][j][0] + bias[128 + c]) * oh0.x,
                                    sigm_f(accB[i][j][1] + bias[128 + c + 1]) * oh0.y);
            float2 v1 = make_float2(sigm_f(accB[i][j][2] + bias[128 + c]) * oh1.x,
                                    sigm_f(accB[i][j][3] + bias[128 + c + 1]) * oh1.y);
            sts_pairf(sb + SM_XHI, sb + SM_XLO, r0, c, v0);
            sts_pairf(sb + SM_XHI, sb + SM_XLO, r0 + 8, c, v1);
        }
    // (sync happens at the top of next GEMM_STEP)

    GEMM_STEP(accA, SM_XHI, SM_XLO, 5);          // A += rh @ Wh[2]
    // epi: ht = tanh(A + b2); z from OUT; mid_h = z*oh + (1-z)*ht -> H tiles
#pragma unroll
    for (int i = 0; i < 2; i++)
#pragma unroll
        for (int j = 0; j < 4; j++) {
            int r0 = erow + i * 16, c = ecol + j * 8;
#pragma unroll
            for (int half = 0; half < 2; half++) {
                int r = r0 + half * 8;
                float2 oh = lds_pairf(sb + SM_HHI, sb + SM_HLO, r, c);
                float2 z  = *(const float2*)(otile + (size_t)r * 128 + c);
                float ht0 = tanh_f(accA[i][j][2 * half]     + bias[256 + c]);
                float ht1 = tanh_f(accA[i][j][2 * half + 1] + bias[256 + c + 1]);
                float2 mh = make_float2(z.x * oh.x + (1.0f - z.x) * ht0,
                                        z.y * oh.y + (1.0f - z.y) * ht1);
                sts_pairf(sb + SM_HHI, sb + SM_HLO, r, c, mh);
            }
        }

    zero_acc(accA);
    GEMM_STEP(accA, SM_HHI, SM_HLO, 6);          // A = mid_h @ mid
    // epi: mid_x = relu(A) -> X tiles
#pragma unroll
    for (int i = 0; i < 2; i++)
#pragma unroll
        for (int j = 0; j < 4; j++) {
            int r0 = erow + i * 16, c = ecol + j * 8;
            sts_pairf(sb + SM_XHI, sb + SM_XLO, r0, c,
                      make_float2(fmaxf(accA[i][j][0], 0.0f), fmaxf(accA[i][j][1], 0.0f)));
            sts_pairf(sb + SM_XHI, sb + SM_XLO, r0 + 8, c,
                      make_float2(fmaxf(accA[i][j][2], 0.0f), fmaxf(accA[i][j][3], 0.0f)));
        }

    // ---------------- stage 2 ----------------
    zero_acc(accA);
    GEMM_STEP(accA, SM_XHI, SM_XLO, 7);          // A  = mid_x @ Wx2[2]
    zero_acc(accB);
    GEMM_STEP(accB, SM_XHI, SM_XLO, 8);          // B  = mid_x @ Wx2[0]
    GEMM_STEP(accB, SM_HHI, SM_HLO, 9);          // B += mid_h @ Wh[0]
    // epi: z2 = sigmoid(B + b0) -> OUT scratch
#pragma unroll
    for (int i = 0; i < 2; i++)
#pragma unroll
        for (int j = 0; j < 4; j++) {
            int r0 = erow + i * 16, c = ecol + j * 8;
            float2 z0 = make_float2(sigm_f(accB[i][j][0] + bias[c]),
                                    sigm_f(accB[i][j][1] + bias[c + 1]));
            float2 z1 = make_float2(sigm_f(accB[i][j][2] + bias[c]),
                                    sigm_f(accB[i][j][3] + bias[c + 1]));
            *(float2*)(otile + (size_t)r0 * 128 + c)       = z0;
            *(float2*)(otile + (size_t)(r0 + 8) * 128 + c) = z1;
        }

    zero_acc(accB);
    GEMM_STEP(accB, SM_XHI, SM_XLO, 10);         // B  = mid_x @ Wx2[1]
    GEMM_STEP(accB, SM_HHI, SM_HLO, 11);         // B += mid_h @ Wh[4]
    // epi: r2 = sigmoid(B + b4); r2h = r2 * mid_h -> X tiles
#pragma unroll
    for (int i = 0; i < 2; i++)
#pragma unroll
        for (int j = 0; j < 4; j++) {
            int r0 = erow + i * 16, c = ecol + j * 8;
            float2 mh0 = lds_pairf(sb + SM_HHI, sb + SM_HLO, r0, c);
            float2 mh1 = lds_pairf(sb + SM_HHI, sb + SM_HLO, r0 + 8, c);
            float2 v0 = make_float2(sigm_f(accB[i][j][0] + bias[512 + c]) * mh0.x,
                                    sigm_f(accB[i][j][1] + bias[512 + c + 1]) * mh0.y);
            float2 v1 = make_float2(sigm_f(accB[i][j][2] + bias[512 + c]) * mh1.x,
                                    sigm_f(accB[i][j][3] + bias[512 + c + 1]) * mh1.y);
            sts_pairf(sb + SM_XHI, sb + SM_XLO, r0, c, v0);
            sts_pairf(sb + SM_XHI, sb + SM_XLO, r0 + 8, c, v1);
        }

    GEMM_STEP(accA, SM_XHI, SM_XLO, 12);         // A += r2h @ Wh[5]
    // final epi: h2t = tanh(A + b5); z2 from OUT; h = z2*mid_h + (1-z2)*h2t -> OUT
#pragma unroll
    for (int i = 0; i < 2; i++)
#pragma unroll
        for (int j = 0; j < 4; j++) {
            int r0 = erow + i * 16, c = ecol + j * 8;
#pragma unroll
            for (int half = 0; half < 2; half++) {
                int r = r0 + half * 8;
                float2 mh = lds_pairf(sb + SM_HHI, sb + SM_HLO, r, c);
                float2 z  = *(const float2*)(otile + (size_t)r * 128 + c);
                float t0 = tanh_f(accA[i][j][2 * half]     + bias[640 + c]);
                float t1 = tanh_f(accA[i][j][2 * half + 1] + bias[640 + c + 1]);
                float2 h = make_float2(z.x * mh.x + (1.0f - z.x) * t0,
                                       z.y * mh.y + (1.0f - z.y) * t1);
                *(float2*)(otile + (size_t)r * 128 + c) = h;
            }
        }
#undef GEMM_STEP
}

// ================================ launch ================================
extern "C" void kernel_launch(void* const* d_in, const int* in_sizes, int n_in,
                              void* d_out, int out_size) {
    const float* x   = (const float*)d_in[0];
    const float* oh  = (const float*)d_in[1];
    const float* wx1 = (const float*)d_in[2];
    const float* wx2 = (const float*)d_in[3];
    const float* wh  = (const float*)d_in[4];
    const float* b   = (const float*)d_in[5];
    const float* mid = (const float*)d_in[6];
    float* out = (float*)d_out;

    cudaFuncSetAttribute(dgru_kernel, cudaFuncAttributeMaxDynamicSharedMemorySize, SM_TOTAL);
    prep_weights<<<(13 * 128 * AST + 255) / 256, 256>>>(wx1, wx2, wh, mid);
    dgru_kernel<<<NTILES, THREADS, SM_TOTAL>>>(x, oh, b, out);
}

// round 10
// speedup vs baseline: 1.5126x; 1.3302x over previous
#include <cuda_runtime.h>
#include <cuda_fp16.h>
#include <cstdint>

// ============================================================================
// DoubleGRU on sm_100 (portable ISA): 13 chained 128x128x128 GEMMs per
// 128-row tile using mma.sync.m16n8k16 fp16 (fp32 accum).
// R10: activations split hi/lo fp16 (exact), weights single fp16 -> 2 fused
// sweeps per GEMM (acc = Ah*B + Al*B), 0.67x MMAs, 0.6x LDSM, 0.5x weight
// stream vs R8. 512 threads, m32n32 warp tiles.
// ============================================================================

#define THREADS 512
#define NTILES  1024
#define AST     136                  // tile stride in fp16 elements (padded)
#define TILE_BYTES (128 * AST * 2)   // 34816

// ---- smem layout (bytes) ----
#define SM_BIAS 0          // 768 floats
#define SM_XHI  4096
#define SM_XLO  (SM_XHI + TILE_BYTES)
#define SM_HHI  (SM_XLO + TILE_BYTES)
#define SM_HLO  (SM_HHI + TILE_BYTES)
#define SM_W0   (SM_HLO + TILE_BYTES)
#define SM_W1   (SM_W0 + TILE_BYTES)
#define SM_TOTAL (SM_W1 + TILE_BYTES)   // 212992

// GEMM g uses weight slot WSLOT[g].
// slots: 0-2 Wx1[i], 3-5 Wx2[i], 6-11 Wh[i], 12 mid
__device__ constexpr int WSLOT[13] = {2, 0, 6, 1, 7, 8, 12, 5, 3, 6, 4, 10, 11};

// Pre-transposed ([n][k], padded to AST) fp16 weight images.
__device__ __align__(256) __half g_w[13][128 * AST];

// ============================== PTX helpers ==============================
__device__ __forceinline__ uint32_t smem_to_u32(const void* p) {
    uint32_t a;
    asm("{ .reg .u64 t; cvta.to.shared.u64 t, %1; cvt.u32.u64 %0, t; }" : "=r"(a) : "l"(p));
    return a;
}

#define WAITG1 asm volatile("cp.async.wait_group 1;" ::: "memory")
#define WAITG0 asm volatile("cp.async.wait_group 0;" ::: "memory")
#define COMMITG asm volatile("cp.async.commit_group;" ::: "memory")

__device__ __forceinline__ void cp_async16(uint32_t dst, const void* src) {
    asm volatile("cp.async.cg.shared.global [%0], [%1], 16;" :: "r"(dst), "l"(src) : "memory");
}

__device__ __forceinline__ void ldm4(uint32_t* r, uint32_t addr) {
    asm volatile("ldmatrix.sync.aligned.m8n8.x4.shared.b16 {%0,%1,%2,%3}, [%4];"
        : "=r"(r[0]), "=r"(r[1]), "=r"(r[2]), "=r"(r[3]) : "r"(addr));
}

__device__ __forceinline__ void mma16816(float* c, const uint32_t* a, const uint32_t* b) {
    asm volatile("mma.sync.aligned.m16n8k16.row.col.f32.f16.f16.f32 "
        "{%0,%1,%2,%3}, {%4,%5,%6,%7}, {%8,%9}, {%0,%1,%2,%3};"
        : "+f"(c[0]), "+f"(c[1]), "+f"(c[2]), "+f"(c[3])
        : "r"(a[0]), "r"(a[1]), "r"(a[2]), "r"(a[3]), "r"(b[0]), "r"(b[1]));
}

// ============================== small math ==============================
__device__ __forceinline__ float sigm_f(float v) {
    v = fminf(fmaxf(v, -30.0f), 30.0f);
    return __fdividef(1.0f, 1.0f + __expf(-v));
}
__device__ __forceinline__ float tanh_f(float v) {
    v = fminf(fmaxf(v, -15.0f), 15.0f);
    float e = __expf(-2.0f * v);
    return __fdividef(1.0f - e, 1.0f + e);
}
__device__ __forceinline__ float2 h2f(uint32_t u) {
    __half2 t = *reinterpret_cast<__half2*>(&u);
    return __half22float2(t);
}

// load/store fp32 pair via hi/lo fp16 tiles (col must be even)
__device__ __forceinline__ float2 lds_pairf(uint32_t hiT, uint32_t loT, int row, int col) {
    uint32_t off = (uint32_t)((row * AST + col) * 2);
    uint32_t h, l;
    asm volatile("ld.shared.u32 %0, [%1];" : "=r"(h) : "r"(hiT + off));
    asm volatile("ld.shared.u32 %0, [%1];" : "=r"(l) : "r"(loT + off));
    float2 a = h2f(h), b = h2f(l);
    return make_float2(a.x + b.x, a.y + b.y);
}
__device__ __forceinline__ void sts_pairf(uint32_t hiT, uint32_t loT, int row, int col, float2 v) {
    __half2 hb = __float22half2_rn(v);
    float2 hf = __half22float2(hb);
    __half2 lb = __float22half2_rn(make_float2(v.x - hf.x, v.y - hf.y));
    uint32_t off = (uint32_t)((row * AST + col) * 2);
    uint32_t hu = *reinterpret_cast<uint32_t*>(&hb);
    uint32_t lu = *reinterpret_cast<uint32_t*>(&lb);
    asm volatile("st.shared.u32 [%0], %1;" :: "r"(hiT + off), "r"(hu) : "memory");
    asm volatile("st.shared.u32 [%0], %1;" :: "r"(loT + off), "r"(lu) : "memory");
}

// ======================= weight prep (fp32 -> fp16, [n][k] padded) =======================
__global__ void prep_weights(const float* __restrict__ wx1, const float* __restrict__ wx2,
                             const float* __restrict__ wh, const float* __restrict__ mid) {
    int idx = blockIdx.x * blockDim.x + threadIdx.x;
    if (idx >= 13 * 128 * AST) return;
    int slot = idx / (128 * AST);
    int r = idx % (128 * AST);
    int n = r / AST;
    int k = r % AST;
    float v = 0.0f;
    if (k < 128) {
        const float* src;
        if (slot < 3)       src = wx1 + slot * 16384;
        else if (slot < 6)  src = wx2 + (slot - 3) * 16384;
        else if (slot < 12) src = wh + (slot - 6) * 16384;
        else                src = mid;
        v = src[k * 128 + n];   // W[k][n] -> B[n][k]
    }
    g_w[slot][n * AST + k] = __float2half_rn(v);
}

// ======================= fused GEMM (m32n32 warp tile) =======================
// acc += Ah*B + Al*B  (exact fp32 activation x fp16 weight)
__device__ __forceinline__ void gemm_fused(uint32_t aH, uint32_t aL, uint32_t bB,
                                           float (*acc)[4][4]) {
#pragma unroll
    for (int k = 0; k < 8; k++) {
        uint32_t A0[4], A1[4], L0[4], L1[4], B0[4], B1[4];
        ldm4(A0, aH + k * 32);
        ldm4(A1, aH + 16 * AST * 2 + k * 32);
        ldm4(L0, aL + k * 32);
        ldm4(L1, aL + 16 * AST * 2 + k * 32);
        ldm4(B0, bB + k * 32);
        ldm4(B1, bB + 16 * AST * 2 + k * 32);
        mma16816(acc[0][0], A0, B0);
        mma16816(acc[0][1], A0, B0 + 2);
        mma16816(acc[0][2], A0, B1);
        mma16816(acc[0][3], A0, B1 + 2);
        mma16816(acc[1][0], A1, B0);
        mma16816(acc[1][1], A1, B0 + 2);
        mma16816(acc[1][2], A1, B1);
        mma16816(acc[1][3], A1, B1 + 2);
        mma16816(acc[0][0], L0, B0);
        mma16816(acc[0][1], L0, B0 + 2);
        mma16816(acc[0][2], L0, B1);
        mma16816(acc[0][3], L0, B1 + 2);
        mma16816(acc[1][0], L1, B0);
        mma16816(acc[1][1], L1, B0 + 2);
        mma16816(acc[1][2], L1, B1);
        mma16816(acc[1][3], L1, B1 + 2);
    }
}

__device__ __forceinline__ void issue_chunk(uint32_t sb, const __half* src,
                                            int tid, int buf) {
    uint32_t dst = sb + (buf ? SM_W1 : SM_W0);
    const char* g = (const char*)src;
#pragma unroll
    for (int off = 0; off < TILE_BYTES; off += THREADS * 16) {
        int o = off + tid * 16;
        if (o < TILE_BYTES) cp_async16(dst + o, g + o);
    }
    COMMITG;
}

__device__ __forceinline__ void zero_acc(float (*acc)[4][4]) {
#pragma unroll
    for (int i = 0; i < 2; i++)
#pragma unroll
        for (int j = 0; j < 4; j++)
#pragma unroll
            for (int e = 0; e < 4; e++) acc[i][j][e] = 0.0f;
}

// ================================ main kernel ================================
__global__ void __launch_bounds__(THREADS, 1)
dgru_kernel(const float* __restrict__ x, const float* __restrict__ h_in,
            const float* __restrict__ bias_g, float* __restrict__ out) {
    extern __shared__ char smem[];
    uint32_t sb = smem_to_u32(smem);
    int tid  = threadIdx.x;
    int lane = tid & 31;
    int wid  = tid >> 5;
    int wm   = wid & 3;    // warp m block (32 rows)
    int wn   = wid >> 2;   // warp n block (32 cols)
    int tile = blockIdx.x;

    // kick off first two weight chunks immediately (chunk g -> buf g&1)
    issue_chunk(sb, &g_w[WSLOT[0]][0], tid, 0);
    issue_chunk(sb, &g_w[WSLOT[1]][0], tid, 1);

    // bias -> smem
    float* bias = (float*)(smem + SM_BIAS);
    for (int i = tid; i < 768; i += THREADS) bias[i] = bias_g[i];

    // prologue: x, old_h -> hi/lo fp16 tiles (each thread: 1 row x 32 cols)
    {
        int prow = tid >> 2, half = (tid & 3) * 32;
        const float4* px = (const float4*)(x    + ((size_t)tile * 128 + prow) * 128 + half);
        const float4* ph = (const float4*)(h_in + ((size_t)tile * 128 + prow) * 128 + half);
#pragma unroll
        for (int c4 = 0; c4 < 8; c4++) {
            float4 v = px[c4];
            sts_pairf(sb + SM_XHI, sb + SM_XLO, prow, half + c4 * 4,     make_float2(v.x, v.y));
            sts_pairf(sb + SM_XHI, sb + SM_XLO, prow, half + c4 * 4 + 2, make_float2(v.z, v.w));
            float4 u = ph[c4];
            sts_pairf(sb + SM_HHI, sb + SM_HLO, prow, half + c4 * 4,     make_float2(u.x, u.y));
            sts_pairf(sb + SM_HHI, sb + SM_HLO, prow, half + c4 * 4 + 2, make_float2(u.z, u.w));
        }
    }

    // per-thread ldmatrix base offsets (bytes within a tile)
    int aro = (lane & 7) + ((lane >> 3) & 1) * 8;
    int ako = ((lane >> 4) & 1) * 8;
    int bro = (lane & 7) + ((lane >> 4) & 1) * 8;
    int bko = ((lane >> 3) & 1) * 8;
    uint32_t aoff = (uint32_t)(((wm * 32 + aro) * AST + ako) * 2);
    uint32_t boff = (uint32_t)(((wn * 32 + bro) * AST + bko) * 2);

    float accA[2][4][4], accB[2][4][4];

    // epilogue element coordinates
    int erow = wm * 32 + (lane >> 2);        // + i*16 (+8 for regs 2,3)
    int ecol = wn * 32 + (lane & 3) * 2;     // + j*8
    float* otile = out + (size_t)tile * 128 * 128;

    // one GEMM with chunk pipelining: chunk g lives in buf g&1; after GEMM g
    // finishes, buf g&1 is refilled with chunk g+2.
#define GEMM_STEP(ACC, AHI, ALO, G) do {                                        \
        if ((G) < 12) { WAITG1; } else { WAITG0; }                              \
        __syncthreads();                                                        \
        gemm_fused(sb + (AHI) + aoff, sb + (ALO) + aoff,                        \
                   sb + (((G) & 1) ? SM_W1 : SM_W0) + boff, ACC);               \
        __syncthreads();                                                        \
        if ((G) < 11) issue_chunk(sb, &g_w[WSLOT[(G) + 2]][0], tid, (G) & 1);   \
    } while (0)

    // ---------------- stage 1 ----------------
    zero_acc(accA);
    GEMM_STEP(accA, SM_XHI, SM_XLO, 0);          // A  = x @ Wx1[2]
    zero_acc(accB);
    GEMM_STEP(accB, SM_XHI, SM_XLO, 1);          // B  = x @ Wx1[0]
    GEMM_STEP(accB, SM_HHI, SM_HLO, 2);          // B += h @ Wh[0]
    // epi: z = sigmoid(B + b0) -> OUT scratch
#pragma unroll
    for (int i = 0; i < 2; i++)
#pragma unroll
        for (int j = 0; j < 4; j++) {
            int r0 = erow + i * 16, c = ecol + j * 8;
            float2 z0 = make_float2(sigm_f(accB[i][j][0] + bias[c]),
                                    sigm_f(accB[i][j][1] + bias[c + 1]));
            float2 z1 = make_float2(sigm_f(accB[i][j][2] + bias[c]),
                                    sigm_f(accB[i][j][3] + bias[c + 1]));
            *(float2*)(otile + (size_t)r0 * 128 + c)       = z0;
            *(float2*)(otile + (size_t)(r0 + 8) * 128 + c) = z1;
        }

    zero_acc(accB);
    GEMM_STEP(accB, SM_XHI, SM_XLO, 3);          // B  = x @ Wx1[1]
    GEMM_STEP(accB, SM_HHI, SM_HLO, 4);          // B += h @ Wh[1]
    // epi: r = sigmoid(B + b1); rh = r * old_h -> X tiles
#pragma unroll
    for (int i = 0; i < 2; i++)
#pragma unroll
        for (int j = 0; j < 4; j++) {
            int r0 = erow + i * 16, c = ecol + j * 8;
            float2 oh0 = lds_pairf(sb + SM_HHI, sb + SM_HLO, r0, c);
            float2 oh1 = lds_pairf(sb + SM_HHI, sb + SM_HLO, r0 + 8, c);
            float2 v0 = make_float2(sigm_f(accB[i][j][0] + bias[128 + c]) * oh0.x,
                                    sigm_f(accB[i][j][1] + bias[128 + c + 1]) * oh0.y);
            float2 v1 = make_float2(sigm_f(accB[i][j][2] + bias[128 + c]) * oh1.x,
                                    sigm_f(accB[i][j][3] + bias[128 + c + 1]) * oh1.y);
            sts_pairf(sb + SM_XHI, sb + SM_XLO, r0, c, v0);
            sts_pairf(sb + SM_XHI, sb + SM_XLO, r0 + 8, c, v1);
        }
    // (sync happens at the top of next GEMM_STEP)

    GEMM_STEP(accA, SM_XHI, SM_XLO, 5);          // A += rh @ Wh[2]
    // epi: ht = tanh(A + b2); z from OUT; mid_h = z*oh + (1-z)*ht -> H tiles
#pragma unroll
    for (int i = 0; i < 2; i++)
#pragma unroll
        for (int j = 0; j < 4; j++) {
            int r0 = erow + i * 16, c = ecol + j * 8;
#pragma unroll
            for (int half = 0; half < 2; half++) {
                int r = r0 + half * 8;
                float2 oh = lds_pairf(sb + SM_HHI, sb + SM_HLO, r, c);
                float2 z  = *(const float2*)(otile + (size_t)r * 128 + c);
                float ht0 = tanh_f(accA[i][j][2 * half]     + bias[256 + c]);
                float ht1 = tanh_f(accA[i][j][2 * half + 1] + bias[256 + c + 1]);
                float2 mh = make_float2(z.x * oh.x + (1.0f - z.x) * ht0,
                                        z.y * oh.y + (1.0f - z.y) * ht1);
                sts_pairf(sb + SM_HHI, sb + SM_HLO, r, c, mh);
            }
        }

    zero_acc(accA);
    GEMM_STEP(accA, SM_HHI, SM_HLO, 6);          // A = mid_h @ mid
    // epi: mid_x = relu(A) -> X tiles
#pragma unroll
    for (int i = 0; i < 2; i++)
#pragma unroll
        for (int j = 0; j < 4; j++) {
            int r0 = erow + i * 16, c = ecol + j * 8;
            sts_pairf(sb + SM_XHI, sb + SM_XLO, r0, c,
                      make_float2(fmaxf(accA[i][j][0], 0.0f), fmaxf(accA[i][j][1], 0.0f)));
            sts_pairf(sb + SM_XHI, sb + SM_XLO, r0 + 8, c,
                      make_float2(fmaxf(accA[i][j][2], 0.0f), fmaxf(accA[i][j][3], 0.0f)));
        }

    // ---------------- stage 2 ----------------
    zero_acc(accA);
    GEMM_STEP(accA, SM_XHI, SM_XLO, 7);          // A  = mid_x @ Wx2[2]
    zero_acc(accB);
    GEMM_STEP(accB, SM_XHI, SM_XLO, 8);          // B  = mid_x @ Wx2[0]
    GEMM_STEP(accB, SM_HHI, SM_HLO, 9);          // B += mid_h @ Wh[0]
    // epi: z2 = sigmoid(B + b0) -> OUT scratch
#pragma unroll
    for (int i = 0; i < 2; i++)
#pragma unroll
        for (int j = 0; j < 4; j++) {
            int r0 = erow + i * 16, c = ecol + j * 8;
            float2 z0 = make_float2(sigm_f(accB[i][j][0] + bias[c]),
                                    sigm_f(accB[i][j][1] + bias[c + 1]));
            float2 z1 = make_float2(sigm_f(accB[i][j][2] + bias[c]),
                                    sigm_f(accB[i][j][3] + bias[c + 1]));
            *(float2*)(otile + (size_t)r0 * 128 + c)       = z0;
            *(float2*)(otile + (size_t)(r0 + 8) * 128 + c) = z1;
        }

    zero_acc(accB);
    GEMM_STEP(accB, SM_XHI, SM_XLO, 10);         // B  = mid_x @ Wx2[1]
    GEMM_STEP(accB, SM_HHI, SM_HLO, 11);         // B += mid_h @ Wh[4]
    // epi: r2 = sigmoid(B + b4); r2h = r2 * mid_h -> X tiles
#pragma unroll
    for (int i = 0; i < 2; i++)
#pragma unroll
        for (int j = 0; j < 4; j++) {
            int r0 = erow + i * 16, c = ecol + j * 8;
            float2 mh0 = lds_pairf(sb + SM_HHI, sb + SM_HLO, r0, c);
            float2 mh1 = lds_pairf(sb + SM_HHI, sb + SM_HLO, r0 + 8, c);
            float2 v0 = make_float2(sigm_f(accB[i][j][0] + bias[512 + c]) * mh0.x,
                                    sigm_f(accB[i][j][1] + bias[512 + c + 1]) * mh0.y);
            float2 v1 = make_float2(sigm_f(accB[i][j][2] + bias[512 + c]) * mh1.x,
                                    sigm_f(accB[i][j][3] + bias[512 + c + 1]) * mh1.y);
            sts_pairf(sb + SM_XHI, sb + SM_XLO, r0, c, v0);
            sts_pairf(sb + SM_XHI, sb + SM_XLO, r0 + 8, c, v1);
        }

    GEMM_STEP(accA, SM_XHI, SM_XLO, 12);         // A += r2h @ Wh[5]
    // final epi: h2t = tanh(A + b5); z2 from OUT; h = z2*mid_h + (1-z2)*h2t -> OUT
#pragma unroll
    for (int i = 0; i < 2; i++)
#pragma unroll
        for (int j = 0; j < 4; j++) {
            int r0 = erow + i * 16, c = ecol + j * 8;
#pragma unroll
            for (int half = 0; half < 2; half++) {
                int r = r0 + half * 8;
                float2 mh = lds_pairf(sb + SM_HHI, sb + SM_HLO, r, c);
                float2 z  = *(const float2*)(otile + (size_t)r * 128 + c);
                float t0 = tanh_f(accA[i][j][2 * half]     + bias[640 + c]);
                float t1 = tanh_f(accA[i][j][2 * half + 1] + bias[640 + c + 1]);
                float2 h = make_float2(z.x * mh.x + (1.0f - z.x) * t0,
                                       z.y * mh.y + (1.0f - z.y) * t1);
                *(float2*)(otile + (size_t)r * 128 + c) = h;
            }
        }
#undef GEMM_STEP
}

// ================================ launch ================================
extern "C" void kernel_launch(void* const* d_in, const int* in_sizes, int n_in,
                              void* d_out, int out_size) {
    const float* x   = (const float*)d_in[0];
    const float* oh  = (const float*)d_in[1];
    const float* wx1 = (const float*)d_in[2];
    const float* wx2 = (const float*)d_in[3];
    const float* wh  = (const float*)d_in[4];
    const float* b   = (const float*)d_in[5];
    const float* mid = (const float*)d_in[6];
    float* out = (float*)d_out;

    cudaFuncSetAttribute(dgru_kernel, cudaFuncAttributeMaxDynamicSharedMemorySize, SM_TOTAL);
    prep_weights<<<(13 * 128 * AST + 255) / 256, 256>>>(wx1, wx2, wh, mid);
    dgru_kernel<<<NTILES, THREADS, SM_TOTAL>>>(x, oh, b, out);
}

// round 11
// speedup vs baseline: 2.2839x; 1.5099x over previous
#include <cuda_runtime.h>
#include <cuda_fp16.h>
#include <cstdint>

// ============================================================================
// DoubleGRU on sm_100 (portable ISA): 13 chained 128x128x128 GEMMs per
// 128-row tile using mma.sync.m16n8k16 fp16 (fp32 accum).
// R11: single fp16 activations x fp16 weights (1 sweep per GEMM, error
// ~3.4e-4 vs 1e-3 gate), z gates kept in smem (no DRAM round-trip).
// 512 threads, m32n32 warp tiles.
// ============================================================================

#define THREADS 512
#define NTILES  1024
#define AST     136                  // activation/weight tile stride (fp16 elems)
#define ZST     132                  // z tile stride (fp32 elems, bank-shifted)
#define TILE_BYTES (128 * AST * 2)   // 34816

// ---- smem layout (bytes) ----
#define SM_BIAS 0                        // 768 floats
#define SM_X    4096
#define SM_H    (SM_X + TILE_BYTES)      // 38912
#define SM_Z    (SM_H + TILE_BYTES)      // 73728 (128 x ZST fp32 = 67584)
#define SM_W0   (SM_Z + 128 * ZST * 4)   // 141312
#define SM_W1   (SM_W0 + TILE_BYTES)     // 176128
#define SM_TOTAL (SM_W1 + TILE_BYTES)    // 210944

// GEMM g uses weight slot WSLOT[g].
// slots: 0-2 Wx1[i], 3-5 Wx2[i], 6-11 Wh[i], 12 mid
__device__ constexpr int WSLOT[13] = {2, 0, 6, 1, 7, 8, 12, 5, 3, 6, 4, 10, 11};

// Pre-transposed ([n][k], padded to AST) fp16 weight images.
__device__ __align__(256) __half g_w[13][128 * AST];

// ============================== PTX helpers ==============================
__device__ __forceinline__ uint32_t smem_to_u32(const void* p) {
    uint32_t a;
    asm("{ .reg .u64 t; cvta.to.shared.u64 t, %1; cvt.u32.u64 %0, t; }" : "=r"(a) : "l"(p));
    return a;
}

#define WAITG1 asm volatile("cp.async.wait_group 1;" ::: "memory")
#define WAITG0 asm volatile("cp.async.wait_group 0;" ::: "memory")
#define COMMITG asm volatile("cp.async.commit_group;" ::: "memory")

__device__ __forceinline__ void cp_async16(uint32_t dst, const void* src) {
    asm volatile("cp.async.cg.shared.global [%0], [%1], 16;" :: "r"(dst), "l"(src) : "memory");
}

__device__ __forceinline__ void ldm4(uint32_t* r, uint32_t addr) {
    asm volatile("ldmatrix.sync.aligned.m8n8.x4.shared.b16 {%0,%1,%2,%3}, [%4];"
        : "=r"(r[0]), "=r"(r[1]), "=r"(r[2]), "=r"(r[3]) : "r"(addr));
}

__device__ __forceinline__ void mma16816(float* c, const uint32_t* a, const uint32_t* b) {
    asm volatile("mma.sync.aligned.m16n8k16.row.col.f32.f16.f16.f32 "
        "{%0,%1,%2,%3}, {%4,%5,%6,%7}, {%8,%9}, {%0,%1,%2,%3};"
        : "+f"(c[0]), "+f"(c[1]), "+f"(c[2]), "+f"(c[3])
        : "r"(a[0]), "r"(a[1]), "r"(a[2]), "r"(a[3]), "r"(b[0]), "r"(b[1]));
}

// ============================== small math ==============================
__device__ __forceinline__ float sigm_f(float v) {
    v = fminf(fmaxf(v, -30.0f), 30.0f);
    return __fdividef(1.0f, 1.0f + __expf(-v));
}
__device__ __forceinline__ float tanh_f(float v) {
    v = fminf(fmaxf(v, -15.0f), 15.0f);
    float e = __expf(-2.0f * v);
    return __fdividef(1.0f - e, 1.0f + e);
}
__device__ __forceinline__ float2 h2f(uint32_t u) {
    __half2 t = *reinterpret_cast<__half2*>(&u);
    return __half22float2(t);
}

// single fp16 tile: load/store fp32 pair (col even)
__device__ __forceinline__ float2 lds_f(uint32_t base, int row, int col) {
    uint32_t off = (uint32_t)((row * AST + col) * 2);
    uint32_t h;
    asm volatile("ld.shared.u32 %0, [%1];" : "=r"(h) : "r"(base + off));
    return h2f(h);
}
__device__ __forceinline__ void sts_f(uint32_t base, int row, int col, float2 v) {
    __half2 hb = __float22half2_rn(v);
    uint32_t off = (uint32_t)((row * AST + col) * 2);
    uint32_t hu = *reinterpret_cast<uint32_t*>(&hb);
    asm volatile("st.shared.u32 [%0], %1;" :: "r"(base + off), "r"(hu) : "memory");
}

// ======================= weight prep (fp32 -> fp16, [n][k] padded) =======================
__global__ void prep_weights(const float* __restrict__ wx1, const float* __restrict__ wx2,
                             const float* __restrict__ wh, const float* __restrict__ mid) {
    int idx = blockIdx.x * blockDim.x + threadIdx.x;
    if (idx >= 13 * 128 * AST) return;
    int slot = idx / (128 * AST);
    int r = idx % (128 * AST);
    int n = r / AST;
    int k = r % AST;
    float v = 0.0f;
    if (k < 128) {
        const float* src;
        if (slot < 3)       src = wx1 + slot * 16384;
        else if (slot < 6)  src = wx2 + (slot - 3) * 16384;
        else if (slot < 12) src = wh + (slot - 6) * 16384;
        else                src = mid;
        v = src[k * 128 + n];   // W[k][n] -> B[n][k]
    }
    g_w[slot][n * AST + k] = __float2half_rn(v);
}

// ======================= GEMM (m32n32 warp tile, single sweep) =======================
__device__ __forceinline__ void gemm_single(uint32_t aT, uint32_t bB, float (*acc)[4][4]) {
#pragma unroll
    for (int k = 0; k < 8; k++) {
        uint32_t A0[4], A1[4], B0[4], B1[4];
        ldm4(A0, aT + k * 32);
        ldm4(A1, aT + 16 * AST * 2 + k * 32);
        ldm4(B0, bB + k * 32);
        ldm4(B1, bB + 16 * AST * 2 + k * 32);
        mma16816(acc[0][0], A0, B0);
        mma16816(acc[0][1], A0, B0 + 2);
        mma16816(acc[0][2], A0, B1);
        mma16816(acc[0][3], A0, B1 + 2);
        mma16816(acc[1][0], A1, B0);
        mma16816(acc[1][1], A1, B0 + 2);
        mma16816(acc[1][2], A1, B1);
        mma16816(acc[1][3], A1, B1 + 2);
    }
}

__device__ __forceinline__ void issue_chunk(uint32_t sb, const __half* src,
                                            int tid, int buf) {
    uint32_t dst = sb + (buf ? SM_W1 : SM_W0);
    const char* g = (const char*)src;
#pragma unroll
    for (int off = 0; off < TILE_BYTES; off += THREADS * 16) {
        int o = off + tid * 16;
        if (o < TILE_BYTES) cp_async16(dst + o, g + o);
    }
    COMMITG;
}

__device__ __forceinline__ void zero_acc(float (*acc)[4][4]) {
#pragma unroll
    for (int i = 0; i < 2; i++)
#pragma unroll
        for (int j = 0; j < 4; j++)
#pragma unroll
            for (int e = 0; e < 4; e++) acc[i][j][e] = 0.0f;
}

// ================================ main kernel ================================
__global__ void __launch_bounds__(THREADS, 1)
dgru_kernel(const float* __restrict__ x, const float* __restrict__ h_in,
            const float* __restrict__ bias_g, float* __restrict__ out) {
    extern __shared__ char smem[];
    uint32_t sb = smem_to_u32(smem);
    int tid  = threadIdx.x;
    int lane = tid & 31;
    int wid  = tid >> 5;
    int wm   = wid & 3;    // warp m block (32 rows)
    int wn   = wid >> 2;   // warp n block (32 cols)
    int tile = blockIdx.x;

    // kick off first two weight chunks immediately (chunk g -> buf g&1)
    issue_chunk(sb, &g_w[WSLOT[0]][0], tid, 0);
    issue_chunk(sb, &g_w[WSLOT[1]][0], tid, 1);

    // bias -> smem
    float* bias = (float*)(smem + SM_BIAS);
    for (int i = tid; i < 768; i += THREADS) bias[i] = bias_g[i];

    // prologue: x, old_h -> fp16 tiles (each thread: 1 row x 32 cols)
    {
        int prow = tid >> 2, half = (tid & 3) * 32;
        const float4* px = (const float4*)(x    + ((size_t)tile * 128 + prow) * 128 + half);
        const float4* ph = (const float4*)(h_in + ((size_t)tile * 128 + prow) * 128 + half);
#pragma unroll
        for (int c4 = 0; c4 < 8; c4++) {
            float4 v = px[c4];
            sts_f(sb + SM_X, prow, half + c4 * 4,     make_float2(v.x, v.y));
            sts_f(sb + SM_X, prow, half + c4 * 4 + 2, make_float2(v.z, v.w));
            float4 u = ph[c4];
            sts_f(sb + SM_H, prow, half + c4 * 4,     make_float2(u.x, u.y));
            sts_f(sb + SM_H, prow, half + c4 * 4 + 2, make_float2(u.z, u.w));
        }
    }

    // per-thread ldmatrix base offsets (bytes within a tile)
    int aro = (lane & 7) + ((lane >> 3) & 1) * 8;
    int ako = ((lane >> 4) & 1) * 8;
    int bro = (lane & 7) + ((lane >> 4) & 1) * 8;
    int bko = ((lane >> 3) & 1) * 8;
    uint32_t aoff = (uint32_t)(((wm * 32 + aro) * AST + ako) * 2);
    uint32_t boff = (uint32_t)(((wn * 32 + bro) * AST + bko) * 2);

    float accA[2][4][4], accB[2][4][4];

    // epilogue element coordinates
    int erow = wm * 32 + (lane >> 2);        // + i*16 (+8 for regs 2,3)
    int ecol = wn * 32 + (lane & 3) * 2;     // + j*8
    float* otile = out + (size_t)tile * 128 * 128;

    // z gate smem accessors (same-thread write/read, no sync needed)
#define Z_ADDR(r, c) (smem + SM_Z + ((size_t)(r) * ZST + (c)) * 4)

    // one GEMM with chunk pipelining: chunk g lives in buf g&1; after GEMM g
    // finishes, buf g&1 is refilled with chunk g+2.
#define GEMM_STEP(ACC, ATILE, G) do {                                           \
        if ((G) < 12) { WAITG1; } else { WAITG0; }                              \
        __syncthreads();                                                        \
        gemm_single(sb + (ATILE) + aoff,                                        \
                    sb + (((G) & 1) ? SM_W1 : SM_W0) + boff, ACC);              \
        __syncthreads();                                                        \
        if ((G) < 11) issue_chunk(sb, &g_w[WSLOT[(G) + 2]][0], tid, (G) & 1);   \
    } while (0)

    // ---------------- stage 1 ----------------
    zero_acc(accA);
    GEMM_STEP(accA, SM_X, 0);            // A  = x @ Wx1[2]
    zero_acc(accB);
    GEMM_STEP(accB, SM_X, 1);            // B  = x @ Wx1[0]
    GEMM_STEP(accB, SM_H, 2);            // B += h @ Wh[0]
    // epi: z = sigmoid(B + b0) -> Z smem
#pragma unroll
    for (int i = 0; i < 2; i++)
#pragma unroll
        for (int j = 0; j < 4; j++) {
            int r0 = erow + i * 16, c = ecol + j * 8;
            *(float2*)Z_ADDR(r0, c) = make_float2(sigm_f(accB[i][j][0] + bias[c]),
                                                  sigm_f(accB[i][j][1] + bias[c + 1]));
            *(float2*)Z_ADDR(r0 + 8, c) = make_float2(sigm_f(accB[i][j][2] + bias[c]),
                                                      sigm_f(accB[i][j][3] + bias[c + 1]));
        }

    zero_acc(accB);
    GEMM_STEP(accB, SM_X, 3);            // B  = x @ Wx1[1]
    GEMM_STEP(accB, SM_H, 4);            // B += h @ Wh[1]
    // epi: r = sigmoid(B + b1); rh = r * old_h -> X tile
#pragma unroll
    for (int i = 0; i < 2; i++)
#pragma unroll
        for (int j = 0; j < 4; j++) {
            int r0 = erow + i * 16, c = ecol + j * 8;
            float2 oh0 = lds_f(sb + SM_H, r0, c);
            float2 oh1 = lds_f(sb + SM_H, r0 + 8, c);
            sts_f(sb + SM_X, r0, c,
                  make_float2(sigm_f(accB[i][j][0] + bias[128 + c]) * oh0.x,
                              sigm_f(accB[i][j][1] + bias[128 + c + 1]) * oh0.y));
            sts_f(sb + SM_X, r0 + 8, c,
                  make_float2(sigm_f(accB[i][j][2] + bias[128 + c]) * oh1.x,
                              sigm_f(accB[i][j][3] + bias[128 + c + 1]) * oh1.y));
        }
    // (sync happens at the top of next GEMM_STEP)

    GEMM_STEP(accA, SM_X, 5);            // A += rh @ Wh[2]
    // epi: ht = tanh(A + b2); z from Z; mid_h = z*oh + (1-z)*ht -> H tile
#pragma unroll
    for (int i = 0; i < 2; i++)
#pragma unroll
        for (int j = 0; j < 4; j++) {
            int r0 = erow + i * 16, c = ecol + j * 8;
#pragma unroll
            for (int half = 0; half < 2; half++) {
                int r = r0 + half * 8;
                float2 oh = lds_f(sb + SM_H, r, c);
                float2 z  = *(const float2*)Z_ADDR(r, c);
                float ht0 = tanh_f(accA[i][j][2 * half]     + bias[256 + c]);
                float ht1 = tanh_f(accA[i][j][2 * half + 1] + bias[256 + c + 1]);
                sts_f(sb + SM_H, r, c,
                      make_float2(z.x * oh.x + (1.0f - z.x) * ht0,
                                  z.y * oh.y + (1.0f - z.y) * ht1));
            }
        }

    zero_acc(accA);
    GEMM_STEP(accA, SM_H, 6);            // A = mid_h @ mid
    // epi: mid_x = relu(A) -> X tile
#pragma unroll
    for (int i = 0; i < 2; i++)
#pragma unroll
        for (int j = 0; j < 4; j++) {
            int r0 = erow + i * 16, c = ecol + j * 8;
            sts_f(sb + SM_X, r0, c,
                  make_float2(fmaxf(accA[i][j][0], 0.0f), fmaxf(accA[i][j][1], 0.0f)));
            sts_f(sb + SM_X, r0 + 8, c,
                  make_float2(fmaxf(accA[i][j][2], 0.0f), fmaxf(accA[i][j][3], 0.0f)));
        }

    // ---------------- stage 2 ----------------
    zero_acc(accA);
    GEMM_STEP(accA, SM_X, 7);            // A  = mid_x @ Wx2[2]
    zero_acc(accB);
    GEMM_STEP(accB, SM_X, 8);            // B  = mid_x @ Wx2[0]
    GEMM_STEP(accB, SM_H, 9);            // B += mid_h @ Wh[0]
    // epi: z2 = sigmoid(B + b0) -> Z smem
#pragma unroll
    for (int i = 0; i < 2; i++)
#pragma unroll
        for (int j = 0; j < 4; j++) {
            int r0 = erow + i * 16, c = ecol + j * 8;
            *(float2*)Z_ADDR(r0, c) = make_float2(sigm_f(accB[i][j][0] + bias[c]),
                                                  sigm_f(accB[i][j][1] + bias[c + 1]));
            *(float2*)Z_ADDR(r0 + 8, c) = make_float2(sigm_f(accB[i][j][2] + bias[c]),
                                                      sigm_f(accB[i][j][3] + bias[c + 1]));
        }

    zero_acc(accB);
    GEMM_STEP(accB, SM_X, 10);           // B  = mid_x @ Wx2[1]
    GEMM_STEP(accB, SM_H, 11);           // B += mid_h @ Wh[4]
    // epi: r2 = sigmoid(B + b4); r2h = r2 * mid_h -> X tile
#pragma unroll
    for (int i = 0; i < 2; i++)
#pragma unroll
        for (int j = 0; j < 4; j++) {
            int r0 = erow + i * 16, c = ecol + j * 8;
            float2 mh0 = lds_f(sb + SM_H, r0, c);
            float2 mh1 = lds_f(sb + SM_H, r0 + 8, c);
            sts_f(sb + SM_X, r0, c,
                  make_float2(sigm_f(accB[i][j][0] + bias[512 + c]) * mh0.x,
                              sigm_f(accB[i][j][1] + bias[512 + c + 1]) * mh0.y));
            sts_f(sb + SM_X, r0 + 8, c,
                  make_float2(sigm_f(accB[i][j][2] + bias[512 + c]) * mh1.x,
                              sigm_f(accB[i][j][3] + bias[512 + c + 1]) * mh1.y));
        }

    GEMM_STEP(accA, SM_X, 12);           // A += r2h @ Wh[5]
    // final epi: h2t = tanh(A + b5); z2 from Z; h = z2*mid_h + (1-z2)*h2t -> OUT
#pragma unroll
    for (int i = 0; i < 2; i++)
#pragma unroll
        for (int j = 0; j < 4; j++) {
            int r0 = erow + i * 16, c = ecol + j * 8;
#pragma unroll
            for (int half = 0; half < 2; half++) {
                int r = r0 + half * 8;
                float2 mh = lds_f(sb + SM_H, r, c);
                float2 z  = *(const float2*)Z_ADDR(r, c);
                float t0 = tanh_f(accA[i][j][2 * half]     + bias[640 + c]);
                float t1 = tanh_f(accA[i][j][2 * half + 1] + bias[640 + c + 1]);
                float2 h = make_float2(z.x * mh.x + (1.0f - z.x) * t0,
                                       z.y * mh.y + (1.0f - z.y) * t1);
                *(float2*)(otile + (size_t)r * 128 + c) = h;
            }
        }
#undef GEMM_STEP
#undef Z_ADDR
}

// ================================ launch ================================
extern "C" void kernel_launch(void* const* d_in, const int* in_sizes, int n_in,
                              void* d_out, int out_size) {
    const float* x   = (const float*)d_in[0];
    const float* oh  = (const float*)d_in[1];
    const float* wx1 = (const float*)d_in[2];
    const float* wx2 = (const float*)d_in[3];
    const float* wh  = (const float*)d_in[4];
    const float* b   = (const float*)d_in[5];
    const float* mid = (const float*)d_in[6];
    float* out = (float*)d_out;

    cudaFuncSetAttribute(dgru_kernel, cudaFuncAttributeMaxDynamicSharedMemorySize, SM_TOTAL);
    prep_weights<<<(13 * 128 * AST + 255) / 256, 256>>>(wx1, wx2, wh, mid);
    dgru_kernel<<<NTILES, THREADS, SM_TOTAL>>>(x, oh, b, out);
}

// round 12
// speedup vs baseline: 2.7333x; 1.1968x over previous
#include <cuda_runtime.h>
#include <cuda_fp16.h>
#include <cstdint>

// ============================================================================
// DoubleGRU on sm_100 (portable ISA): 13 chained 128x128x128 GEMMs per
// 128-row tile using mma.sync.m16n8k16 fp16 (fp32 accum).
// R12: one __syncthreads per GEMM (refill at top of next step), MUFU.TANH
// epilogues (sigmoid = 0.5+0.5*tanh(v/2)), z gates in fp16 smem.
// 512 threads, m32n32 warp tiles.
// ============================================================================

#define THREADS 512
#define NTILES  1024
#define AST     136                  // tile stride (fp16 elems, padded)
#define TILE_BYTES (128 * AST * 2)   // 34816

// ---- smem layout (bytes) ----
#define SM_BIAS 0                        // 768 floats
#define SM_X    4096
#define SM_H    (SM_X + TILE_BYTES)      // 38912
#define SM_Z    (SM_H + TILE_BYTES)      // 73728 (fp16 tile)
#define SM_W0   (SM_Z + TILE_BYTES)      // 108544
#define SM_W1   (SM_W0 + TILE_BYTES)     // 143360
#define SM_TOTAL (SM_W1 + TILE_BYTES)    // 178176

// GEMM g uses weight slot WSLOT[g].
// slots: 0-2 Wx1[i], 3-5 Wx2[i], 6-11 Wh[i], 12 mid
__device__ constexpr int WSLOT[13] = {2, 0, 6, 1, 7, 8, 12, 5, 3, 6, 4, 10, 11};

// Pre-transposed ([n][k], padded to AST) fp16 weight images.
__device__ __align__(256) __half g_w[13][128 * AST];

// ============================== PTX helpers ==============================
__device__ __forceinline__ uint32_t smem_to_u32(const void* p) {
    uint32_t a;
    asm("{ .reg .u64 t; cvta.to.shared.u64 t, %1; cvt.u32.u64 %0, t; }" : "=r"(a) : "l"(p));
    return a;
}

#define WAITG1 asm volatile("cp.async.wait_group 1;" ::: "memory")
#define WAITG0 asm volatile("cp.async.wait_group 0;" ::: "memory")
#define COMMITG asm volatile("cp.async.commit_group;" ::: "memory")

__device__ __forceinline__ void cp_async16(uint32_t dst, const void* src) {
    asm volatile("cp.async.cg.shared.global [%0], [%1], 16;" :: "r"(dst), "l"(src) : "memory");
}

__device__ __forceinline__ void ldm4(uint32_t* r, uint32_t addr) {
    asm volatile("ldmatrix.sync.aligned.m8n8.x4.shared.b16 {%0,%1,%2,%3}, [%4];"
        : "=r"(r[0]), "=r"(r[1]), "=r"(r[2]), "=r"(r[3]) : "r"(addr));
}

__device__ __forceinline__ void mma16816(float* c, const uint32_t* a, const uint32_t* b) {
    asm volatile("mma.sync.aligned.m16n8k16.row.col.f32.f16.f16.f32 "
        "{%0,%1,%2,%3}, {%4,%5,%6,%7}, {%8,%9}, {%0,%1,%2,%3};"
        : "+f"(c[0]), "+f"(c[1]), "+f"(c[2]), "+f"(c[3])
        : "r"(a[0]), "r"(a[1]), "r"(a[2]), "r"(a[3]), "r"(b[0]), "r"(b[1]));
}

// ============================== small math ==============================
__device__ __forceinline__ float tanh_f(float v) {
    float r;
    asm("tanh.approx.f32 %0, %1;" : "=f"(r) : "f"(v));
    return r;
}
__device__ __forceinline__ float sigm_f(float v) {
    return fmaf(tanh_f(v * 0.5f), 0.5f, 0.5f);
}
__device__ __forceinline__ float2 h2f(uint32_t u) {
    __half2 t = *reinterpret_cast<__half2*>(&u);
    return __half22float2(t);
}

// fp16 tile: load/store fp32 pair (col even)
__device__ __forceinline__ float2 lds_f(uint32_t base, int row, int col) {
    uint32_t off = (uint32_t)((row * AST + col) * 2);
    uint32_t h;
    asm volatile("ld.shared.u32 %0, [%1];" : "=r"(h) : "r"(base + off));
    return h2f(h);
}
__device__ __forceinline__ void sts_f(uint32_t base, int row, int col, float2 v) {
    __half2 hb = __float22half2_rn(v);
    uint32_t off = (uint32_t)((row * AST + col) * 2);
    uint32_t hu = *reinterpret_cast<uint32_t*>(&hb);
    asm volatile("st.shared.u32 [%0], %1;" :: "r"(base + off), "r"(hu) : "memory");
}

// ======================= weight prep (fp32 -> fp16, [n][k] padded) =======================
__global__ void prep_weights(const float* __restrict__ wx1, const float* __restrict__ wx2,
                             const float* __restrict__ wh, const float* __restrict__ mid) {
    int idx = blockIdx.x * blockDim.x + threadIdx.x;
    if (idx >= 13 * 128 * AST) return;
    int slot = idx / (128 * AST);
    int r = idx % (128 * AST);
    int n = r / AST;
    int k = r % AST;
    float v = 0.0f;
    if (k < 128) {
        const float* src;
        if (slot < 3)       src = wx1 + slot * 16384;
        else if (slot < 6)  src = wx2 + (slot - 3) * 16384;
        else if (slot < 12) src = wh + (slot - 6) * 16384;
        else                src = mid;
        v = src[k * 128 + n];   // W[k][n] -> B[n][k]
    }
    g_w[slot][n * AST + k] = __float2half_rn(v);
}

// ======================= GEMM (m32n32 warp tile, single sweep) =======================
__device__ __forceinline__ void gemm_single(uint32_t aT, uint32_t bB, float (*acc)[4][4]) {
#pragma unroll
    for (int k = 0; k < 8; k++) {
        uint32_t A0[4], A1[4], B0[4], B1[4];
        ldm4(A0, aT + k * 32);
        ldm4(A1, aT + 16 * AST * 2 + k * 32);
        ldm4(B0, bB + k * 32);
        ldm4(B1, bB + 16 * AST * 2 + k * 32);
        mma16816(acc[0][0], A0, B0);
        mma16816(acc[0][1], A0, B0 + 2);
        mma16816(acc[0][2], A0, B1);
        mma16816(acc[0][3], A0, B1 + 2);
        mma16816(acc[1][0], A1, B0);
        mma16816(acc[1][1], A1, B0 + 2);
        mma16816(acc[1][2], A1, B1);
        mma16816(acc[1][3], A1, B1 + 2);
    }
}

__device__ __forceinline__ void issue_chunk(uint32_t sb, const __half* src,
                                            int tid, int buf) {
    uint32_t dst = sb + (buf ? SM_W1 : SM_W0);
    const char* g = (const char*)src;
#pragma unroll
    for (int off = 0; off < TILE_BYTES; off += THREADS * 16) {
        int o = off + tid * 16;
        if (o < TILE_BYTES) cp_async16(dst + o, g + o);
    }
    COMMITG;
}

__device__ __forceinline__ void zero_acc(float (*acc)[4][4]) {
#pragma unroll
    for (int i = 0; i < 2; i++)
#pragma unroll
        for (int j = 0; j < 4; j++)
#pragma unroll
            for (int e = 0; e < 4; e++) acc[i][j][e] = 0.0f;
}

// ================================ main kernel ================================
__global__ void __launch_bounds__(THREADS, 1)
dgru_kernel(const float* __restrict__ x, const float* __restrict__ h_in,
            const float* __restrict__ bias_g, float* __restrict__ out) {
    extern __shared__ char smem[];
    uint32_t sb = smem_to_u32(smem);
    int tid  = threadIdx.x;
    int lane = tid & 31;
    int wid  = tid >> 5;
    int wm   = wid & 3;    // warp m block (32 rows)
    int wn   = wid >> 2;   // warp n block (32 cols)
    int tile = blockIdx.x;

    // kick off first two weight chunks immediately (chunk g -> buf g&1)
    issue_chunk(sb, &g_w[WSLOT[0]][0], tid, 0);
    issue_chunk(sb, &g_w[WSLOT[1]][0], tid, 1);

    // bias -> smem
    float* bias = (float*)(smem + SM_BIAS);
    for (int i = tid; i < 768; i += THREADS) bias[i] = bias_g[i];

    // prologue: x, old_h -> fp16 tiles (each thread: 1 row x 32 cols)
    {
        int prow = tid >> 2, half = (tid & 3) * 32;
        const float4* px = (const float4*)(x    + ((size_t)tile * 128 + prow) * 128 + half);
        const float4* ph = (const float4*)(h_in + ((size_t)tile * 128 + prow) * 128 + half);
#pragma unroll
        for (int c4 = 0; c4 < 8; c4++) {
            float4 v = px[c4];
            sts_f(sb + SM_X, prow, half + c4 * 4,     make_float2(v.x, v.y));
            sts_f(sb + SM_X, prow, half + c4 * 4 + 2, make_float2(v.z, v.w));
            float4 u = ph[c4];
            sts_f(sb + SM_H, prow, half + c4 * 4,     make_float2(u.x, u.y));
            sts_f(sb + SM_H, prow, half + c4 * 4 + 2, make_float2(u.z, u.w));
        }
    }

    // per-thread ldmatrix base offsets (bytes within a tile)
    int aro = (lane & 7) + ((lane >> 3) & 1) * 8;
    int ako = ((lane >> 4) & 1) * 8;
    int bro = (lane & 7) + ((lane >> 4) & 1) * 8;
    int bko = ((lane >> 3) & 1) * 8;
    uint32_t aoff = (uint32_t)(((wm * 32 + aro) * AST + ako) * 2);
    uint32_t boff = (uint32_t)(((wn * 32 + bro) * AST + bko) * 2);

    float accA[2][4][4], accB[2][4][4];

    // epilogue element coordinates
    int erow = wm * 32 + (lane >> 2);        // + i*16 (+8 for regs 2,3)
    int ecol = wn * 32 + (lane & 3) * 2;     // + j*8
    float* otile = out + (size_t)tile * 128 * 128;

    // One GEMM per step, ONE sync per step. Entry sync proves all warps are
    // done with GEMM g-1 (which read buf (g-1)&1 = (g+1)&1), so we refill that
    // buffer with chunk g+1 here, then wait for chunk g (one group back).
#define GEMM_STEP(ACC, ATILE, G) do {                                           \
        __syncthreads();                                                        \
        if ((G) >= 1 && (G) <= 11) issue_chunk(sb, &g_w[WSLOT[(G) + 1]][0], tid, ((G) + 1) & 1); \
        if ((G) < 12) { WAITG1; } else { WAITG0; }                              \
        gemm_single(sb + (ATILE) + aoff,                                        \
                    sb + (((G) & 1) ? SM_W1 : SM_W0) + boff, ACC);              \
    } while (0)

    // ---------------- stage 1 ----------------
    zero_acc(accA);
    GEMM_STEP(accA, SM_X, 0);            // A  = x @ Wx1[2]
    zero_acc(accB);
    GEMM_STEP(accB, SM_X, 1);            // B  = x @ Wx1[0]
    GEMM_STEP(accB, SM_H, 2);            // B += h @ Wh[0]
    // epi: z = sigmoid(B + b0) -> Z smem (fp16, same-thread read later)
#pragma unroll
    for (int i = 0; i < 2; i++)
#pragma unroll
        for (int j = 0; j < 4; j++) {
            int r0 = erow + i * 16, c = ecol + j * 8;
            sts_f(sb + SM_Z, r0, c, make_float2(sigm_f(accB[i][j][0] + bias[c]),
                                                sigm_f(accB[i][j][1] + bias[c + 1])));
            sts_f(sb + SM_Z, r0 + 8, c, make_float2(sigm_f(accB[i][j][2] + bias[c]),
                                                    sigm_f(accB[i][j][3] + bias[c + 1])));
        }

    zero_acc(accB);
    GEMM_STEP(accB, SM_X, 3);            // B  = x @ Wx1[1]
    GEMM_STEP(accB, SM_H, 4);            // B += h @ Wh[1]
    // epi: r = sigmoid(B + b1); rh = r * old_h -> X tile
#pragma unroll
    for (int i = 0; i < 2; i++)
#pragma unroll
        for (int j = 0; j < 4; j++) {
            int r0 = erow + i * 16, c = ecol + j * 8;
            float2 oh0 = lds_f(sb + SM_H, r0, c);
            float2 oh1 = lds_f(sb + SM_H, r0 + 8, c);
            sts_f(sb + SM_X, r0, c,
                  make_float2(sigm_f(accB[i][j][0] + bias[128 + c]) * oh0.x,
                              sigm_f(accB[i][j][1] + bias[128 + c + 1]) * oh0.y));
            sts_f(sb + SM_X, r0 + 8, c,
                  make_float2(sigm_f(accB[i][j][2] + bias[128 + c]) * oh1.x,
                              sigm_f(accB[i][j][3] + bias[128 + c + 1]) * oh1.y));
        }

    GEMM_STEP(accA, SM_X, 5);            // A += rh @ Wh[2]
    // epi: ht = tanh(A + b2); z from Z; mid_h = z*oh + (1-z)*ht -> H tile
#pragma unroll
    for (int i = 0; i < 2; i++)
#pragma unroll
        for (int j = 0; j < 4; j++) {
            int r0 = erow + i * 16, c = ecol + j * 8;
#pragma unroll
            for (int half = 0; half < 2; half++) {
                int r = r0 + half * 8;
                float2 oh = lds_f(sb + SM_H, r, c);
                float2 z  = lds_f(sb + SM_Z, r, c);
                float ht0 = tanh_f(accA[i][j][2 * half]     + bias[256 + c]);
                float ht1 = tanh_f(accA[i][j][2 * half + 1] + bias[256 + c + 1]);
                sts_f(sb + SM_H, r, c,
                      make_float2(z.x * oh.x + (1.0f - z.x) * ht0,
                                  z.y * oh.y + (1.0f - z.y) * ht1));
            }
        }

    zero_acc(accA);
    GEMM_STEP(accA, SM_H, 6);            // A = mid_h @ mid
    // epi: mid_x = relu(A) -> X tile
#pragma unroll
    for (int i = 0; i < 2; i++)
#pragma unroll
        for (int j = 0; j < 4; j++) {
            int r0 = erow + i * 16, c = ecol + j * 8;
            sts_f(sb + SM_X, r0, c,
                  make_float2(fmaxf(accA[i][j][0], 0.0f), fmaxf(accA[i][j][1], 0.0f)));
            sts_f(sb + SM_X, r0 + 8, c,
                  make_float2(fmaxf(accA[i][j][2], 0.0f), fmaxf(accA[i][j][3], 0.0f)));
        }

    // ---------------- stage 2 ----------------
    zero_acc(accA);
    GEMM_STEP(accA, SM_X, 7);            // A  = mid_x @ Wx2[2]
    zero_acc(accB);
    GEMM_STEP(accB, SM_X, 8);            // B  = mid_x @ Wx2[0]
    GEMM_STEP(accB, SM_H, 9);            // B += mid_h @ Wh[0]
    // epi: z2 = sigmoid(B + b0) -> Z smem
#pragma unroll
    for (int i = 0; i < 2; i++)
#pragma unroll
        for (int j = 0; j < 4; j++) {
            int r0 = erow + i * 16, c = ecol + j * 8;
            sts_f(sb + SM_Z, r0, c, make_float2(sigm_f(accB[i][j][0] + bias[c]),
                                                sigm_f(accB[i][j][1] + bias[c + 1])));
            sts_f(sb + SM_Z, r0 + 8, c, make_float2(sigm_f(accB[i][j][2] + bias[c]),
                                                    sigm_f(accB[i][j][3] + bias[c + 1])));
        }

    zero_acc(accB);
    GEMM_STEP(accB, SM_X, 10);           // B  = mid_x @ Wx2[1]
    GEMM_STEP(accB, SM_H, 11);           // B += mid_h @ Wh[4]
    // epi: r2 = sigmoid(B + b4); r2h = r2 * mid_h -> X tile
#pragma unroll
    for (int i = 0; i < 2; i++)
#pragma unroll
        for (int j = 0; j < 4; j++) {
            int r0 = erow + i * 16, c = ecol + j * 8;
            float2 mh0 = lds_f(sb + SM_H, r0, c);
            float2 mh1 = lds_f(sb + SM_H, r0 + 8, c);
            sts_f(sb + SM_X, r0, c,
                  make_float2(sigm_f(accB[i][j][0] + bias[512 + c]) * mh0.x,
                              sigm_f(accB[i][j][1] + bias[512 + c + 1]) * mh0.y));
            sts_f(sb + SM_X, r0 + 8, c,
                  make_float2(sigm_f(accB[i][j][2] + bias[512 + c]) * mh1.x,
                              sigm_f(accB[i][j][3] + bias[512 + c + 1]) * mh1.y));
        }

    GEMM_STEP(accA, SM_X, 12);           // A += r2h @ Wh[5]
    // final epi: h2t = tanh(A + b5); z2 from Z; h = z2*mid_h + (1-z2)*h2t -> OUT
#pragma unroll
    for (int i = 0; i < 2; i++)
#pragma unroll
        for (int j = 0; j < 4; j++) {
            int r0 = erow + i * 16, c = ecol + j * 8;
#pragma unroll
            for (int half = 0; half < 2; half++) {
                int r = r0 + half * 8;
                float2 mh = lds_f(sb + SM_H, r, c);
                float2 z  = lds_f(sb + SM_Z, r, c);
                float t0 = tanh_f(accA[i][j][2 * half]     + bias[640 + c]);
                float t1 = tanh_f(accA[i][j][2 * half + 1] + bias[640 + c + 1]);
                float2 h = make_float2(z.x * mh.x + (1.0f - z.x) * t0,
                                       z.y * mh.y + (1.0f - z.y) * t1);
                *(float2*)(otile + (size_t)r * 128 + c) = h;
            }
        }
#undef GEMM_STEP
}

// ================================ launch ================================
extern "C" void kernel_launch(void* const* d_in, const int* in_sizes, int n_in,
                              void* d_out, int out_size) {
    const float* x   = (const float*)d_in[0];
    const float* oh  = (const float*)d_in[1];
    const float* wx1 = (const float*)d_in[2];
    const float* wx2 = (const float*)d_in[3];
    const float* wh  = (const float*)d_in[4];
    const float* b   = (const float*)d_in[5];
    const float* mid = (const float*)d_in[6];
    float* out = (float*)d_out;

    cudaFuncSetAttribute(dgru_kernel, cudaFuncAttributeMaxDynamicSharedMemorySize, SM_TOTAL);
    prep_weights<<<(13 * 128 * AST + 255) / 256, 256>>>(wx1, wx2, wh, mid);
    dgru_kernel<<<NTILES, THREADS, SM_TOTAL>>>(x, oh, b, out);
}